// round 7
// baseline (speedup 1.0000x reference)
#include <cuda_runtime.h>

#define NN 20000
#define EE 320000
#define GG 200
#define FF 128

// ---- scratch (static device globals: allocation-free at runtime) ----
__device__ float g_x[NN * FF];            // node features
__device__ float g_P[NN * 768];           // per-node gate/mlp projections [Ag|Bg|Cg|Am|Bm|Cm]
__device__ float g_Y[NN * 384];           // per-node [y_p1|y_p2|y_psi]
__device__ float g_pool[GG * FF];         // accumulated pools
__device__ float g_Bcat[3 * 128 * 768];   // packed gate/mlp weights per block
__device__ float g_Bpool[3 * 128 * 384];  // packed pool/psi weights per block

typedef unsigned long long ull;

__device__ __forceinline__ float sigm(float v) { return 1.0f / (1.0f + __expf(-v)); }
__device__ __forceinline__ float eluf(float v) { return v > 0.f ? v : (__expf(v) - 1.0f); }

__device__ __forceinline__ void fma2(ull& acc, ull a, ull b) {
    asm("fma.rn.f32x2 %0, %1, %2, %0;" : "+l"(acc) : "l"(a), "l"(b));
}
__device__ __forceinline__ ull mul2(ull a, ull b) {
    ull r; asm("mul.rn.f32x2 %0, %1, %2;" : "=l"(r) : "l"(a), "l"(b)); return r;
}
__device__ __forceinline__ float2 unp(ull v) {
    float2 r; asm("mov.b64 {%0,%1}, %2;" : "=f"(r.x), "=f"(r.y) : "l"(v)); return r;
}
__device__ __forceinline__ ull pk(float a, float b) {
    ull r; asm("mov.b64 %0, {%1,%2};" : "=l"(r) : "f"(a), "f"(b)); return r;
}

// =====================================================================
// GEMM: C[M,N] = act(A[M,128] @ B[128,N]); N % 128 == 0
// Scalar FFMA. BM=64, BN=128, BK=32, 256 threads, 4x8 micro-tile.
// ~60 regs, 25.6KB smem -> 4 CTAs/SM (32 warps). FMA-bound by design:
// per k-iter: 4 LDS.32(bcast) + 2 LDS.128 + 32 FFMA (84% fma density).
// =====================================================================
__global__ __launch_bounds__(256) void gemmS_kernel(
    const float* __restrict__ A, const float* __restrict__ B, float* __restrict__ C,
    int M, int N, int act)
{
    __shared__ float As[64][36];     // [m][k] padded  (9.2 KB)
    __shared__ float Bs[32][128];    // [k][n]         (16 KB)

    int m0 = blockIdx.x * 64;
    int n0 = blockIdx.y * 128;
    int tid = threadIdx.x;
    int tx = tid & 15;               // col group (8 cols: tx*8)
    int ty = tid >> 4;               // row group (4 rows: ty*4)

    float acc[4][8];
    #pragma unroll
    for (int i = 0; i < 4; i++)
        #pragma unroll
        for (int j = 0; j < 8; j++) acc[i][j] = 0.f;

    // staging indices
    int ar = tid >> 2;               // A row 0..63
    int ak = (tid & 3) * 8;          // k sub-chunk (0,8,16,24)
    int br = tid >> 3;               // B k-row 0..31
    int bc = (tid & 7) * 16;         // B col group

    bool mok = (m0 + ar) < M;
    const float* Ap = A + (size_t)(m0 + ar) * 128 + ak;

    for (int kt = 0; kt < 4; kt++) {
        // stage A: 8 consecutive k-floats of one row
        {
            float4 v0 = make_float4(0.f, 0.f, 0.f, 0.f);
            float4 v1 = make_float4(0.f, 0.f, 0.f, 0.f);
            if (mok) {
                v0 = *(const float4*)(Ap + kt * 32);
                v1 = *(const float4*)(Ap + kt * 32 + 4);
            }
            *(float4*)(&As[ar][ak])     = v0;
            *(float4*)(&As[ar][ak + 4]) = v1;
        }
        // stage B: one k-row, 16 cols
        {
            const float* Bp = B + (size_t)(kt * 32 + br) * N + n0 + bc;
            #pragma unroll
            for (int j = 0; j < 4; j++)
                *(float4*)(&Bs[br][bc + j * 4]) = *(const float4*)(Bp + j * 4);
        }
        __syncthreads();

        #pragma unroll
        for (int k = 0; k < 32; k++) {
            float a0 = As[ty * 4 + 0][k];
            float a1 = As[ty * 4 + 1][k];
            float a2 = As[ty * 4 + 2][k];
            float a3 = As[ty * 4 + 3][k];
            float4 b0 = *(float4*)(&Bs[k][tx * 8]);
            float4 b1 = *(float4*)(&Bs[k][tx * 8 + 4]);
            acc[0][0] += a0 * b0.x; acc[0][1] += a0 * b0.y; acc[0][2] += a0 * b0.z; acc[0][3] += a0 * b0.w;
            acc[0][4] += a0 * b1.x; acc[0][5] += a0 * b1.y; acc[0][6] += a0 * b1.z; acc[0][7] += a0 * b1.w;
            acc[1][0] += a1 * b0.x; acc[1][1] += a1 * b0.y; acc[1][2] += a1 * b0.z; acc[1][3] += a1 * b0.w;
            acc[1][4] += a1 * b1.x; acc[1][5] += a1 * b1.y; acc[1][6] += a1 * b1.z; acc[1][7] += a1 * b1.w;
            acc[2][0] += a2 * b0.x; acc[2][1] += a2 * b0.y; acc[2][2] += a2 * b0.z; acc[2][3] += a2 * b0.w;
            acc[2][4] += a2 * b1.x; acc[2][5] += a2 * b1.y; acc[2][6] += a2 * b1.z; acc[2][7] += a2 * b1.w;
            acc[3][0] += a3 * b0.x; acc[3][1] += a3 * b0.y; acc[3][2] += a3 * b0.z; acc[3][3] += a3 * b0.w;
            acc[3][4] += a3 * b1.x; acc[3][5] += a3 * b1.y; acc[3][6] += a3 * b1.z; acc[3][7] += a3 * b1.w;
        }
        __syncthreads();
    }

    #pragma unroll
    for (int i = 0; i < 4; i++) {
        int m = m0 + ty * 4 + i;
        if (m < M) {
            float r[8];
            #pragma unroll
            for (int j = 0; j < 8; j++) r[j] = acc[i][j];
            if (act == 1) {
                #pragma unroll
                for (int j = 0; j < 8; j++) r[j] = sigm(r[j]);
            }
            float* Cp = C + (size_t)m * N + n0 + tx * 8;
            *(float4*)Cp = make_float4(r[0], r[1], r[2], r[3]);
            *(float4*)(Cp + 4) = make_float4(r[4], r[5], r[6], r[7]);
        }
    }
}

// =====================================================================
// Weight packing (recomputed every call)
// =====================================================================
__global__ void pack_gates_kernel(const float* __restrict__ Wg, const float* __restrict__ Wm)
{
    int idx = blockIdx.x * blockDim.x + threadIdx.x;
    if (idx >= 3 * 128 * 768) return;
    int j = idx % 768;
    int k = (idx / 768) % 128;
    int i = idx / (768 * 128);
    int b = j >> 7, c = j & 127;
    float v;
    if (b < 3) v = Wg[(size_t)i * 384 * 128 + (size_t)(b * 128 + k) * 128 + c];
    else       v = Wm[(size_t)i * 384 * 128 + (size_t)((b - 3) * 128 + k) * 128 + c];
    g_Bcat[idx] = v;
}

__global__ void pack_pool_kernel(const float* __restrict__ Wp1, const float* __restrict__ Wp2,
                                 const float* __restrict__ Wpsi)
{
    int idx = blockIdx.x * blockDim.x + threadIdx.x;
    if (idx >= 3 * 128 * 384) return;
    int j = idx % 384;
    int k = (idx / 384) % 128;
    int i = idx / (384 * 128);
    int b = j >> 7, c = j & 127;
    const float* W = (b == 0) ? Wp1 : (b == 1) ? Wp2 : Wpsi;
    g_Bpool[idx] = W[(size_t)i * 128 * 128 + (size_t)k * 128 + c];
}

__global__ void zero_pool_kernel()
{
    int i = blockIdx.x * blockDim.x + threadIdx.x;
    if (i < GG * FF) g_pool[i] = 0.f;
}

// =====================================================================
// Edge kernel: tiles of 64 edges per CTA iter, 8 edges per warp.
// Weights in smem (fp32); coefficients staged as duplicated float2 so
// one broadcast LDS.128 delivers two packed f32x2 scalars.
// z2g -> sigmoid -> z2*s -> + z1 ; gate/gather/scatter per edge.
// =====================================================================
__global__ __launch_bounds__(256) void edge_kernel(
    const int* __restrict__ esrc, const int* __restrict__ etgt,
    const float* __restrict__ edist,
    const float* __restrict__ cs, const float* __restrict__ pw,
    const float* __restrict__ W1v, const float* __restrict__ W2v,
    const float* __restrict__ W2vg, int E)
{
    extern __shared__ float smem[];
    float*  sW = smem;                       // 88*128 floats = 45056 B
    float2* sC = (float2*)(smem + 88 * 128); // [64 edges][64 kslots] dup'd = 32768 B

    // stage weights once per CTA: rows 0..35 W1v, 36..61 W2v, 62..87 W2vg
    for (int i = threadIdx.x; i < 36 * 128; i += 256) sW[i] = W1v[i];
    for (int i = threadIdx.x; i < 26 * 128; i += 256) sW[36 * 128 + i] = W2v[i];
    for (int i = threadIdx.x; i < 26 * 128; i += 256) sW[62 * 128 + i] = W2vg[i];
    __syncthreads();

    int tid = threadIdx.x;
    int lane = tid & 31;
    int warp = tid >> 5;
    int f0 = lane * 4;
    int eb = warp * 8;
    int ntiles = (E + 63) >> 6;

    for (int tile = blockIdx.x; tile < ntiles; tile += gridDim.x) {
        int e0 = tile * 64;
        // stage coefficients (duplicated)
        for (int idx = tid; idx < 64 * 36; idx += 256) {
            int e = idx / 36, k = idx % 36;
            if (e0 + e < E) {
                float v = cs[(size_t)(e0 + e) * 36 + k];
                sC[e * 64 + k] = make_float2(v, v);
            }
        }
        for (int idx = tid; idx < 64 * 26; idx += 256) {
            int e = idx / 26, k = idx % 26;
            if (e0 + e < E) {
                float v = pw[(size_t)(e0 + e) * 26 + k];
                sC[e * 64 + 36 + k] = make_float2(v, v);
            }
        }
        __syncthreads();

        // ---- phase A: zg = pw @ W2vg ----
        ull zg[8][2];
        #pragma unroll
        for (int e = 0; e < 8; e++) { zg[e][0] = 0ull; zg[e][1] = 0ull; }
        for (int kc = 0; kc < 13; kc++) {
            float4 w0 = *(float4*)(&sW[(62 + kc * 2) * 128 + f0]);
            float4 w1 = *(float4*)(&sW[(63 + kc * 2) * 128 + f0]);
            ull w0a = ((ull*)&w0)[0], w0b = ((ull*)&w0)[1];
            ull w1a = ((ull*)&w1)[0], w1b = ((ull*)&w1)[1];
            #pragma unroll
            for (int e = 0; e < 8; e++) {
                float4 cc = *(float4*)(&sC[(eb + e) * 64 + 36 + kc * 2]);
                ull c0 = ((ull*)&cc)[0], c1 = ((ull*)&cc)[1];
                fma2(zg[e][0], c0, w0a); fma2(zg[e][1], c0, w0b);
                fma2(zg[e][0], c1, w1a); fma2(zg[e][1], c1, w1b);
            }
        }
        // sigmoid
        ull ss[8][2];
        #pragma unroll
        for (int e = 0; e < 8; e++) {
            #pragma unroll
            for (int h = 0; h < 2; h++) {
                float2 v = unp(zg[e][h]);
                ss[e][h] = pk(sigm(v.x), sigm(v.y));
            }
        }

        // ---- phase B: za = pw @ W2v, then za *= ss ----
        ull za[8][2];
        #pragma unroll
        for (int e = 0; e < 8; e++) { za[e][0] = 0ull; za[e][1] = 0ull; }
        for (int kc = 0; kc < 13; kc++) {
            float4 w0 = *(float4*)(&sW[(36 + kc * 2) * 128 + f0]);
            float4 w1 = *(float4*)(&sW[(37 + kc * 2) * 128 + f0]);
            ull w0a = ((ull*)&w0)[0], w0b = ((ull*)&w0)[1];
            ull w1a = ((ull*)&w1)[0], w1b = ((ull*)&w1)[1];
            #pragma unroll
            for (int e = 0; e < 8; e++) {
                float4 cc = *(float4*)(&sC[(eb + e) * 64 + 36 + kc * 2]);
                ull c0 = ((ull*)&cc)[0], c1 = ((ull*)&cc)[1];
                fma2(za[e][0], c0, w0a); fma2(za[e][1], c0, w0b);
                fma2(za[e][0], c1, w1a); fma2(za[e][1], c1, w1b);
            }
        }
        #pragma unroll
        for (int e = 0; e < 8; e++) {
            za[e][0] = mul2(za[e][0], ss[e][0]);
            za[e][1] = mul2(za[e][1], ss[e][1]);
        }

        // ---- phase C: za += cs @ W1v ----
        for (int kc = 0; kc < 18; kc++) {
            float4 w0 = *(float4*)(&sW[(kc * 2) * 128 + f0]);
            float4 w1 = *(float4*)(&sW[(kc * 2 + 1) * 128 + f0]);
            ull w0a = ((ull*)&w0)[0], w0b = ((ull*)&w0)[1];
            ull w1a = ((ull*)&w1)[0], w1b = ((ull*)&w1)[1];
            #pragma unroll
            for (int e = 0; e < 8; e++) {
                float4 cc = *(float4*)(&sC[(eb + e) * 64 + kc * 2]);
                ull c0 = ((ull*)&cc)[0], c1 = ((ull*)&cc)[1];
                fma2(za[e][0], c0, w0a); fma2(za[e][1], c0, w0b);
                fma2(za[e][0], c1, w1a); fma2(za[e][1], c1, w1b);
            }
        }

        // ---- gate phase ----
        int sreg = 0, treg = 0; float dreg = 1.f;
        if (lane < 8 && (e0 + eb + lane) < E) {
            sreg = esrc[e0 + eb + lane];
            treg = etgt[e0 + eb + lane];
            dreg = edist[e0 + eb + lane];
        }
        #pragma unroll
        for (int e = 0; e < 8; e++) {
            int s = __shfl_sync(0xffffffffu, sreg, e);
            int t = __shfl_sync(0xffffffffu, treg, e);
            float invd = 1.0f / __shfl_sync(0xffffffffu, dreg, e);
            if ((e0 + eb + e) < E) {
                const float* Ps = g_P + (size_t)s * 768;
                const float* Pt = g_P + (size_t)t * 768;
                float4 ag  = *(const float4*)(Ps + f0);
                float4 bg  = *(const float4*)(Pt + 128 + f0);
                float4 cgs = *(const float4*)(Ps + 256 + f0);
                float4 cgt = *(const float4*)(Pt + 256 + f0);
                float4 am  = *(const float4*)(Ps + 384 + f0);
                float4 bm  = *(const float4*)(Pt + 512 + f0);
                float4 cms = *(const float4*)(Ps + 640 + f0);
                float4 cmt = *(const float4*)(Pt + 640 + f0);

                float2 za0 = unp(za[e][0]);
                float2 za1 = unp(za[e][1]);
                float zv[4] = { za0.x, za0.y, za1.x, za1.y };
                float gv[4], mv[4];
                gv[0] = sigm(ag.x + bg.x + (cgt.x - cgs.x) * invd);
                gv[1] = sigm(ag.y + bg.y + (cgt.y - cgs.y) * invd);
                gv[2] = sigm(ag.z + bg.z + (cgt.z - cgs.z) * invd);
                gv[3] = sigm(ag.w + bg.w + (cgt.w - cgs.w) * invd);
                mv[0] = eluf(am.x + bm.x + (cmt.x - cms.x) * invd);
                mv[1] = eluf(am.y + bm.y + (cmt.y - cms.y) * invd);
                mv[2] = eluf(am.z + bm.z + (cmt.z - cms.z) * invd);
                mv[3] = eluf(am.w + bm.w + (cmt.w - cms.w) * invd);

                float* xr = g_x + (size_t)s * 128 + f0;
                #pragma unroll
                for (int j = 0; j < 4; j++)
                    atomicAdd(xr + j, gv[j] * mv[j] * zv[j]);
            }
        }
        __syncthreads();
    }
}

// =====================================================================
// Pool + psi: per node, pool[g] += elu(y1)*y2 ; x = elu(y3)
// =====================================================================
__global__ __launch_bounds__(256) void poolpsi_kernel(const int* __restrict__ gidx, int N)
{
    int lane = threadIdx.x & 31;
    int f0 = lane * 4;
    int warp = blockIdx.x * 8 + (threadIdx.x >> 5);
    int nw = gridDim.x * 8;
    for (int n = warp; n < N; n += nw) {
        int g = gidx[n];
        const float* yr = g_Y + (size_t)n * 384;
        float y1[4], y2[4], y3[4];
        *(float4*)y1 = *(const float4*)(yr + f0);
        *(float4*)y2 = *(const float4*)(yr + 128 + f0);
        *(float4*)y3 = *(const float4*)(yr + 256 + f0);
        float* pr = g_pool + (size_t)g * 128 + f0;
        #pragma unroll
        for (int j = 0; j < 4; j++) atomicAdd(pr + j, eluf(y1[j]) * y2[j]);
        float xo[4];
        #pragma unroll
        for (int j = 0; j < 4; j++) xo[j] = eluf(y3[j]);
        *(float4*)(g_x + (size_t)n * 128 + f0) = *(float4*)xo;
    }
}

// =====================================================================
// Final MLP: one warp per graph.  128 -> 64 -> 42 -> 1
// =====================================================================
__global__ __launch_bounds__(256) void final_kernel(
    const float* __restrict__ W1, const float* __restrict__ W2,
    const float* __restrict__ W3, float* __restrict__ out, int G)
{
    int lane = threadIdx.x & 31;
    int warp = blockIdx.x * 8 + (threadIdx.x >> 5);
    int nw = gridDim.x * 8;
    for (int g = warp; g < G; g += nw) {
        float pr[4];
        #pragma unroll
        for (int c = 0; c < 4; c++) pr[c] = g_pool[(size_t)g * 128 + c * 32 + lane];

        float a0 = 0.f, a1 = 0.f;
        #pragma unroll
        for (int c = 0; c < 4; c++) {
            #pragma unroll
            for (int kk = 0; kk < 32; kk++) {
                float v = __shfl_sync(0xffffffffu, pr[c], kk);
                int k = c * 32 + kk;
                a0 += v * W1[k * 64 + lane * 2];
                a1 += v * W1[k * 64 + lane * 2 + 1];
            }
        }
        a0 = eluf(a0); a1 = eluf(a1);

        float b0 = 0.f, b1 = 0.f;
        #pragma unroll
        for (int k = 0; k < 64; k++) {
            float v = __shfl_sync(0xffffffffu, (k & 1) ? a1 : a0, k >> 1);
            b0 += v * W2[k * 42 + lane];
            if (lane < 10) b1 += v * W2[k * 42 + 32 + lane];
        }
        b0 = eluf(b0);
        if (lane < 10) b1 = eluf(b1);

        float r = b0 * W3[lane] + ((lane < 10) ? b1 * W3[32 + lane] : 0.f);
        #pragma unroll
        for (int o = 16; o; o >>= 1) r += __shfl_xor_sync(0xffffffffu, r, o);
        if (lane == 0) out[g] = r;
    }
}

// =====================================================================
extern "C" void kernel_launch(void* const* d_in, const int* in_sizes, int n_in,
                              void* d_out, int out_size)
{
    (void)n_in; (void)out_size;
    const float* nodes  = (const float*)d_in[0];
    const int*   esrc   = (const int*)d_in[1];
    const int*   etgt   = (const int*)d_in[2];
    const float* edist  = (const float*)d_in[3];
    const int*   gidx   = (const int*)d_in[4];
    const float* cs     = (const float*)d_in[6];
    const float* pw     = (const float*)d_in[7];
    const float* W_emb  = (const float*)d_in[8];
    const float* Wg     = (const float*)d_in[9];
    const float* Wm     = (const float*)d_in[10];
    const float* W1v    = (const float*)d_in[11];
    const float* W2v    = (const float*)d_in[12];
    const float* W2vg   = (const float*)d_in[13];
    const float* Wp1    = (const float*)d_in[14];
    const float* Wp2    = (const float*)d_in[15];
    const float* Wpsi   = (const float*)d_in[16];
    const float* Wlr1   = (const float*)d_in[17];
    const float* Wlr2   = (const float*)d_in[18];
    const float* Wlr3   = (const float*)d_in[19];
    float* out = (float*)d_out;

    int N = in_sizes[0] / FF;       // 20000
    int E = in_sizes[1];            // 320000
    int G = in_sizes[5];            // 200

    float *px, *pP, *pY, *pBcat, *pBpool;
    cudaGetSymbolAddress((void**)&px, g_x);
    cudaGetSymbolAddress((void**)&pP, g_P);
    cudaGetSymbolAddress((void**)&pY, g_Y);
    cudaGetSymbolAddress((void**)&pBcat, g_Bcat);
    cudaGetSymbolAddress((void**)&pBpool, g_Bpool);

    static int smem_set = 0;
    const int EDGE_SMEM = 88 * 128 * 4 + 64 * 64 * 8;  // 77824 B
    if (!smem_set) {
        cudaFuncSetAttribute(edge_kernel, cudaFuncAttributeMaxDynamicSharedMemorySize, EDGE_SMEM);
        smem_set = 1;
    }

    // prep
    pack_gates_kernel<<<(3 * 128 * 768 + 255) / 256, 256>>>(Wg, Wm);
    pack_pool_kernel<<<(3 * 128 * 384 + 255) / 256, 256>>>(Wp1, Wp2, Wpsi);
    zero_pool_kernel<<<(GG * FF + 255) / 256, 256>>>();

    int mg = (N + 63) / 64;   // 313

    // embedding: x = sigmoid(nodes @ W_emb)
    gemmS_kernel<<<dim3(mg, 1), 256>>>(nodes, W_emb, px, N, 128, 1);

    for (int i = 0; i < 3; i++) {
        // node-side gate/mlp projections: P = x @ Bcat[i]   [N, 768]
        gemmS_kernel<<<dim3(mg, 6), 256>>>(px, pBcat + (size_t)i * 128 * 768, pP, N, 768, 0);
        // edge pass: scatter-add z into x
        edge_kernel<<<296, 256, EDGE_SMEM>>>(esrc, etgt, edist, cs, pw,
                                             W1v + (size_t)i * 36 * 128,
                                             W2v + (size_t)i * 26 * 128,
                                             W2vg + (size_t)i * 26 * 128, E);
        // pool/psi projections: Y = x @ Bpool[i]   [N, 384]
        gemmS_kernel<<<dim3(mg, 3), 256>>>(px, pBpool + (size_t)i * 128 * 384, pY, N, 384, 0);
        // pool accumulation + x = elu(x @ Wpsi)
        poolpsi_kernel<<<625, 256>>>(gidx, N);
    }

    final_kernel<<<(G + 7) / 8, 256>>>(Wlr1, Wlr2, Wlr3, out, G);
}

// round 8
// speedup vs baseline: 1.7304x; 1.7304x over previous
#include <cuda_runtime.h>

#define NN 20000
#define EE 320000
#define GG 200
#define FF 128

// ---- scratch (static device globals: allocation-free at runtime) ----
__device__ float g_x[NN * FF];            // node features
__device__ float g_P[NN * 768];           // per-node gate/mlp projections [Ag|Bg|Cg|Am|Bm|Cm]
__device__ float g_Y[NN * 384];           // per-node [y_p1|y_p2|y_psi]
__device__ float g_pool[GG * FF];         // accumulated pools
__device__ float g_Bcat[3 * 128 * 768];   // packed gate/mlp weights per block
__device__ float g_Bpool[3 * 128 * 384];  // packed pool/psi weights per block

typedef unsigned long long ull;

__device__ __forceinline__ float sigm(float v) { return 1.0f / (1.0f + __expf(-v)); }
__device__ __forceinline__ float eluf(float v) { return v > 0.f ? v : (__expf(v) - 1.0f); }

__device__ __forceinline__ void fma2(ull& acc, ull a, ull b) {
    asm("fma.rn.f32x2 %0, %1, %2, %0;" : "+l"(acc) : "l"(a), "l"(b));
}
__device__ __forceinline__ ull mul2(ull a, ull b) {
    ull r; asm("mul.rn.f32x2 %0, %1, %2;" : "=l"(r) : "l"(a), "l"(b)); return r;
}
__device__ __forceinline__ float2 unp(ull v) {
    float2 r; asm("mov.b64 {%0,%1}, %2;" : "=f"(r.x), "=f"(r.y) : "l"(v)); return r;
}
__device__ __forceinline__ ull pk(float a, float b) {
    ull r; asm("mov.b64 %0, {%1,%2};" : "=l"(r) : "f"(a), "f"(b)); return r;
}

// =====================================================================
// Generic GEMM (R3-proven): C[M,N] = act(A[M,128] @ B[128,N]); N % 64 == 0
// BM=64, BN=64, BK=64 (2 k-tiles), 256 threads, 4x4 micro-tile
// =====================================================================
__global__ __launch_bounds__(256) void gemm128_kernel(
    const float* __restrict__ A, const float* __restrict__ B, float* __restrict__ C,
    int M, int N, int act)
{
    __shared__ float As[64][68];   // [m][k], padded: conflict-free scalar a-reads
    __shared__ float Bs[64][64];   // [k][n]

    int m0 = blockIdx.x * 64;
    int n0 = blockIdx.y * 64;
    int tid = threadIdx.x;
    int tx = tid & 15, ty = tid >> 4;

    float acc[4][4] = {};

    for (int kt = 0; kt < 2; kt++) {
        int k0 = kt * 64;
        #pragma unroll
        for (int i = 0; i < 4; i++) {
            int idx = tid + i * 256;        // 0..1023
            int r = idx >> 4;               // 0..63
            int cv = idx & 15;              // float4 within 64
            int m = m0 + r;
            float4 va = make_float4(0.f, 0.f, 0.f, 0.f);
            if (m < M) va = *(const float4*)(A + (size_t)m * 128 + k0 + cv * 4);
            *(float4*)(&As[r][cv * 4]) = va;
            float4 vb = *(const float4*)(B + (size_t)(k0 + r) * N + n0 + cv * 4);
            *(float4*)(&Bs[r][cv * 4]) = vb;
        }
        __syncthreads();
        #pragma unroll 8
        for (int k = 0; k < 64; k++) {
            float a0 = As[ty * 4 + 0][k];
            float a1 = As[ty * 4 + 1][k];
            float a2 = As[ty * 4 + 2][k];
            float a3 = As[ty * 4 + 3][k];
            float4 b = *(float4*)(&Bs[k][tx * 4]);
            acc[0][0] += a0 * b.x; acc[0][1] += a0 * b.y; acc[0][2] += a0 * b.z; acc[0][3] += a0 * b.w;
            acc[1][0] += a1 * b.x; acc[1][1] += a1 * b.y; acc[1][2] += a1 * b.z; acc[1][3] += a1 * b.w;
            acc[2][0] += a2 * b.x; acc[2][1] += a2 * b.y; acc[2][2] += a2 * b.z; acc[2][3] += a2 * b.w;
            acc[3][0] += a3 * b.x; acc[3][1] += a3 * b.y; acc[3][2] += a3 * b.z; acc[3][3] += a3 * b.w;
        }
        __syncthreads();
    }

    #pragma unroll
    for (int i = 0; i < 4; i++) {
        int m = m0 + ty * 4 + i;
        if (m < M) {
            float4 r;
            r.x = acc[i][0]; r.y = acc[i][1]; r.z = acc[i][2]; r.w = acc[i][3];
            if (act == 1) { r.x = sigm(r.x); r.y = sigm(r.y); r.z = sigm(r.z); r.w = sigm(r.w); }
            *(float4*)(C + (size_t)m * N + n0 + tx * 4) = r;
        }
    }
}

// =====================================================================
// Weight packing (recomputed every call)
// =====================================================================
__global__ void pack_gates_kernel(const float* __restrict__ Wg, const float* __restrict__ Wm)
{
    int idx = blockIdx.x * blockDim.x + threadIdx.x;
    if (idx >= 3 * 128 * 768) return;
    int j = idx % 768;
    int k = (idx / 768) % 128;
    int i = idx / (768 * 128);
    int b = j >> 7, c = j & 127;
    float v;
    if (b < 3) v = Wg[(size_t)i * 384 * 128 + (size_t)(b * 128 + k) * 128 + c];
    else       v = Wm[(size_t)i * 384 * 128 + (size_t)((b - 3) * 128 + k) * 128 + c];
    g_Bcat[idx] = v;
}

__global__ void pack_pool_kernel(const float* __restrict__ Wp1, const float* __restrict__ Wp2,
                                 const float* __restrict__ Wpsi)
{
    int idx = blockIdx.x * blockDim.x + threadIdx.x;
    if (idx >= 3 * 128 * 384) return;
    int j = idx % 384;
    int k = (idx / 384) % 128;
    int i = idx / (384 * 128);
    int b = j >> 7, c = j & 127;
    const float* W = (b == 0) ? Wp1 : (b == 1) ? Wp2 : Wpsi;
    g_Bpool[idx] = W[(size_t)i * 128 * 128 + (size_t)k * 128 + c];
}

__global__ void zero_pool_kernel()
{
    int i = blockIdx.x * blockDim.x + threadIdx.x;
    if (i < GG * FF) g_pool[i] = 0.f;
}

// =====================================================================
// Edge kernel (R5-proven): tiles of 64 edges per CTA iter, 8 edges/warp.
// Weights in smem (fp32); coefficients staged as duplicated float2 so
// one broadcast LDS.128 delivers two packed f32x2 scalars.
// z2g -> sigmoid -> z2*s -> + z1 ; gate/gather/scatter per edge.
// =====================================================================
__global__ __launch_bounds__(256) void edge_kernel(
    const int* __restrict__ esrc, const int* __restrict__ etgt,
    const float* __restrict__ edist,
    const float* __restrict__ cs, const float* __restrict__ pw,
    const float* __restrict__ W1v, const float* __restrict__ W2v,
    const float* __restrict__ W2vg, int E)
{
    extern __shared__ float smem[];
    float*  sW = smem;                       // 88*128 floats = 45056 B
    float2* sC = (float2*)(smem + 88 * 128); // [64 edges][64 kslots] dup'd = 32768 B

    // stage weights once per CTA: rows 0..35 W1v, 36..61 W2v, 62..87 W2vg
    for (int i = threadIdx.x; i < 36 * 128; i += 256) sW[i] = W1v[i];
    for (int i = threadIdx.x; i < 26 * 128; i += 256) sW[36 * 128 + i] = W2v[i];
    for (int i = threadIdx.x; i < 26 * 128; i += 256) sW[62 * 128 + i] = W2vg[i];
    __syncthreads();

    int tid = threadIdx.x;
    int lane = tid & 31;
    int warp = tid >> 5;
    int f0 = lane * 4;
    int eb = warp * 8;
    int ntiles = (E + 63) >> 6;

    for (int tile = blockIdx.x; tile < ntiles; tile += gridDim.x) {
        int e0 = tile * 64;
        // stage coefficients (duplicated)
        for (int idx = tid; idx < 64 * 36; idx += 256) {
            int e = idx / 36, k = idx % 36;
            if (e0 + e < E) {
                float v = cs[(size_t)(e0 + e) * 36 + k];
                sC[e * 64 + k] = make_float2(v, v);
            }
        }
        for (int idx = tid; idx < 64 * 26; idx += 256) {
            int e = idx / 26, k = idx % 26;
            if (e0 + e < E) {
                float v = pw[(size_t)(e0 + e) * 26 + k];
                sC[e * 64 + 36 + k] = make_float2(v, v);
            }
        }
        __syncthreads();

        // ---- phase A: zg = pw @ W2vg ----
        ull zg[8][2];
        #pragma unroll
        for (int e = 0; e < 8; e++) { zg[e][0] = 0ull; zg[e][1] = 0ull; }
        for (int kc = 0; kc < 13; kc++) {
            float4 w0 = *(float4*)(&sW[(62 + kc * 2) * 128 + f0]);
            float4 w1 = *(float4*)(&sW[(63 + kc * 2) * 128 + f0]);
            ull w0a = ((ull*)&w0)[0], w0b = ((ull*)&w0)[1];
            ull w1a = ((ull*)&w1)[0], w1b = ((ull*)&w1)[1];
            #pragma unroll
            for (int e = 0; e < 8; e++) {
                float4 cc = *(float4*)(&sC[(eb + e) * 64 + 36 + kc * 2]);
                ull c0 = ((ull*)&cc)[0], c1 = ((ull*)&cc)[1];
                fma2(zg[e][0], c0, w0a); fma2(zg[e][1], c0, w0b);
                fma2(zg[e][0], c1, w1a); fma2(zg[e][1], c1, w1b);
            }
        }
        // sigmoid
        ull ss[8][2];
        #pragma unroll
        for (int e = 0; e < 8; e++) {
            #pragma unroll
            for (int h = 0; h < 2; h++) {
                float2 v = unp(zg[e][h]);
                ss[e][h] = pk(sigm(v.x), sigm(v.y));
            }
        }

        // ---- phase B: za = pw @ W2v, then za *= ss ----
        ull za[8][2];
        #pragma unroll
        for (int e = 0; e < 8; e++) { za[e][0] = 0ull; za[e][1] = 0ull; }
        for (int kc = 0; kc < 13; kc++) {
            float4 w0 = *(float4*)(&sW[(36 + kc * 2) * 128 + f0]);
            float4 w1 = *(float4*)(&sW[(37 + kc * 2) * 128 + f0]);
            ull w0a = ((ull*)&w0)[0], w0b = ((ull*)&w0)[1];
            ull w1a = ((ull*)&w1)[0], w1b = ((ull*)&w1)[1];
            #pragma unroll
            for (int e = 0; e < 8; e++) {
                float4 cc = *(float4*)(&sC[(eb + e) * 64 + 36 + kc * 2]);
                ull c0 = ((ull*)&cc)[0], c1 = ((ull*)&cc)[1];
                fma2(za[e][0], c0, w0a); fma2(za[e][1], c0, w0b);
                fma2(za[e][0], c1, w1a); fma2(za[e][1], c1, w1b);
            }
        }
        #pragma unroll
        for (int e = 0; e < 8; e++) {
            za[e][0] = mul2(za[e][0], ss[e][0]);
            za[e][1] = mul2(za[e][1], ss[e][1]);
        }

        // ---- phase C: za += cs @ W1v ----
        for (int kc = 0; kc < 18; kc++) {
            float4 w0 = *(float4*)(&sW[(kc * 2) * 128 + f0]);
            float4 w1 = *(float4*)(&sW[(kc * 2 + 1) * 128 + f0]);
            ull w0a = ((ull*)&w0)[0], w0b = ((ull*)&w0)[1];
            ull w1a = ((ull*)&w1)[0], w1b = ((ull*)&w1)[1];
            #pragma unroll
            for (int e = 0; e < 8; e++) {
                float4 cc = *(float4*)(&sC[(eb + e) * 64 + kc * 2]);
                ull c0 = ((ull*)&cc)[0], c1 = ((ull*)&cc)[1];
                fma2(za[e][0], c0, w0a); fma2(za[e][1], c0, w0b);
                fma2(za[e][0], c1, w1a); fma2(za[e][1], c1, w1b);
            }
        }

        // ---- gate phase ----
        int sreg = 0, treg = 0; float dreg = 1.f;
        if (lane < 8 && (e0 + eb + lane) < E) {
            sreg = esrc[e0 + eb + lane];
            treg = etgt[e0 + eb + lane];
            dreg = edist[e0 + eb + lane];
        }
        #pragma unroll
        for (int e = 0; e < 8; e++) {
            int s = __shfl_sync(0xffffffffu, sreg, e);
            int t = __shfl_sync(0xffffffffu, treg, e);
            float invd = 1.0f / __shfl_sync(0xffffffffu, dreg, e);
            if ((e0 + eb + e) < E) {
                const float* Ps = g_P + (size_t)s * 768;
                const float* Pt = g_P + (size_t)t * 768;
                float4 ag  = *(const float4*)(Ps + f0);
                float4 bg  = *(const float4*)(Pt + 128 + f0);
                float4 cgs = *(const float4*)(Ps + 256 + f0);
                float4 cgt = *(const float4*)(Pt + 256 + f0);
                float4 am  = *(const float4*)(Ps + 384 + f0);
                float4 bm  = *(const float4*)(Pt + 512 + f0);
                float4 cms = *(const float4*)(Ps + 640 + f0);
                float4 cmt = *(const float4*)(Pt + 640 + f0);

                float2 za0 = unp(za[e][0]);
                float2 za1 = unp(za[e][1]);
                float zv[4] = { za0.x, za0.y, za1.x, za1.y };
                float gv[4], mv[4];
                gv[0] = sigm(ag.x + bg.x + (cgt.x - cgs.x) * invd);
                gv[1] = sigm(ag.y + bg.y + (cgt.y - cgs.y) * invd);
                gv[2] = sigm(ag.z + bg.z + (cgt.z - cgs.z) * invd);
                gv[3] = sigm(ag.w + bg.w + (cgt.w - cgs.w) * invd);
                mv[0] = eluf(am.x + bm.x + (cmt.x - cms.x) * invd);
                mv[1] = eluf(am.y + bm.y + (cmt.y - cms.y) * invd);
                mv[2] = eluf(am.z + bm.z + (cmt.z - cms.z) * invd);
                mv[3] = eluf(am.w + bm.w + (cmt.w - cms.w) * invd);

                float* xr = g_x + (size_t)s * 128 + f0;
                #pragma unroll
                for (int j = 0; j < 4; j++)
                    atomicAdd(xr + j, gv[j] * mv[j] * zv[j]);
            }
        }
        __syncthreads();
    }
}

// =====================================================================
// Pool + psi: per node, pool[g] += elu(y1)*y2 ; x = elu(y3)
// =====================================================================
__global__ __launch_bounds__(256) void poolpsi_kernel(const int* __restrict__ gidx, int N)
{
    int lane = threadIdx.x & 31;
    int f0 = lane * 4;
    int warp = blockIdx.x * 8 + (threadIdx.x >> 5);
    int nw = gridDim.x * 8;
    for (int n = warp; n < N; n += nw) {
        int g = gidx[n];
        const float* yr = g_Y + (size_t)n * 384;
        float y1[4], y2[4], y3[4];
        *(float4*)y1 = *(const float4*)(yr + f0);
        *(float4*)y2 = *(const float4*)(yr + 128 + f0);
        *(float4*)y3 = *(const float4*)(yr + 256 + f0);
        float* pr = g_pool + (size_t)g * 128 + f0;
        #pragma unroll
        for (int j = 0; j < 4; j++) atomicAdd(pr + j, eluf(y1[j]) * y2[j]);
        float xo[4];
        #pragma unroll
        for (int j = 0; j < 4; j++) xo[j] = eluf(y3[j]);
        *(float4*)(g_x + (size_t)n * 128 + f0) = *(float4*)xo;
    }
}

// =====================================================================
// Final MLP: one warp per graph.  128 -> 64 -> 42 -> 1
// =====================================================================
__global__ __launch_bounds__(256) void final_kernel(
    const float* __restrict__ W1, const float* __restrict__ W2,
    const float* __restrict__ W3, float* __restrict__ out, int G)
{
    int lane = threadIdx.x & 31;
    int warp = blockIdx.x * 8 + (threadIdx.x >> 5);
    int nw = gridDim.x * 8;
    for (int g = warp; g < G; g += nw) {
        float pr[4];
        #pragma unroll
        for (int c = 0; c < 4; c++) pr[c] = g_pool[(size_t)g * 128 + c * 32 + lane];

        float a0 = 0.f, a1 = 0.f;
        #pragma unroll
        for (int c = 0; c < 4; c++) {
            #pragma unroll
            for (int kk = 0; kk < 32; kk++) {
                float v = __shfl_sync(0xffffffffu, pr[c], kk);
                int k = c * 32 + kk;
                a0 += v * W1[k * 64 + lane * 2];
                a1 += v * W1[k * 64 + lane * 2 + 1];
            }
        }
        a0 = eluf(a0); a1 = eluf(a1);

        float b0 = 0.f, b1 = 0.f;
        #pragma unroll
        for (int k = 0; k < 64; k++) {
            float v = __shfl_sync(0xffffffffu, (k & 1) ? a1 : a0, k >> 1);
            b0 += v * W2[k * 42 + lane];
            if (lane < 10) b1 += v * W2[k * 42 + 32 + lane];
        }
        b0 = eluf(b0);
        if (lane < 10) b1 = eluf(b1);

        float r = b0 * W3[lane] + ((lane < 10) ? b1 * W3[32 + lane] : 0.f);
        #pragma unroll
        for (int o = 16; o; o >>= 1) r += __shfl_xor_sync(0xffffffffu, r, o);
        if (lane == 0) out[g] = r;
    }
}

// =====================================================================
extern "C" void kernel_launch(void* const* d_in, const int* in_sizes, int n_in,
                              void* d_out, int out_size)
{
    (void)n_in; (void)out_size;
    const float* nodes  = (const float*)d_in[0];
    const int*   esrc   = (const int*)d_in[1];
    const int*   etgt   = (const int*)d_in[2];
    const float* edist  = (const float*)d_in[3];
    const int*   gidx   = (const int*)d_in[4];
    const float* cs     = (const float*)d_in[6];
    const float* pw     = (const float*)d_in[7];
    const float* W_emb  = (const float*)d_in[8];
    const float* Wg     = (const float*)d_in[9];
    const float* Wm     = (const float*)d_in[10];
    const float* W1v    = (const float*)d_in[11];
    const float* W2v    = (const float*)d_in[12];
    const float* W2vg   = (const float*)d_in[13];
    const float* Wp1    = (const float*)d_in[14];
    const float* Wp2    = (const float*)d_in[15];
    const float* Wpsi   = (const float*)d_in[16];
    const float* Wlr1   = (const float*)d_in[17];
    const float* Wlr2   = (const float*)d_in[18];
    const float* Wlr3   = (const float*)d_in[19];
    float* out = (float*)d_out;

    int N = in_sizes[0] / FF;       // 20000
    int E = in_sizes[1];            // 320000
    int G = in_sizes[5];            // 200

    float *px, *pP, *pY, *pBcat, *pBpool;
    cudaGetSymbolAddress((void**)&px, g_x);
    cudaGetSymbolAddress((void**)&pP, g_P);
    cudaGetSymbolAddress((void**)&pY, g_Y);
    cudaGetSymbolAddress((void**)&pBcat, g_Bcat);
    cudaGetSymbolAddress((void**)&pBpool, g_Bpool);

    static int smem_set = 0;
    const int EDGE_SMEM = 88 * 128 * 4 + 64 * 64 * 8;  // 77824 B
    if (!smem_set) {
        cudaFuncSetAttribute(edge_kernel, cudaFuncAttributeMaxDynamicSharedMemorySize, EDGE_SMEM);
        smem_set = 1;
    }

    // prep
    pack_gates_kernel<<<(3 * 128 * 768 + 255) / 256, 256>>>(Wg, Wm);
    pack_pool_kernel<<<(3 * 128 * 384 + 255) / 256, 256>>>(Wp1, Wp2, Wpsi);
    zero_pool_kernel<<<(GG * FF + 255) / 256, 256>>>();

    int mg = (N + 63) / 64;   // 313

    // embedding: x = sigmoid(nodes @ W_emb)
    gemm128_kernel<<<dim3(mg, 2), 256>>>(nodes, W_emb, px, N, 128, 1);

    for (int i = 0; i < 3; i++) {
        // node-side gate/mlp projections: P = x @ Bcat[i]   [N, 768]
        gemm128_kernel<<<dim3(mg, 12), 256>>>(px, pBcat + (size_t)i * 128 * 768, pP, N, 768, 0);
        // edge pass: scatter-add z into x
        edge_kernel<<<296, 256, EDGE_SMEM>>>(esrc, etgt, edist, cs, pw,
                                             W1v + (size_t)i * 36 * 128,
                                             W2v + (size_t)i * 26 * 128,
                                             W2vg + (size_t)i * 26 * 128, E);
        // pool/psi projections: Y = x @ Bpool[i]   [N, 384]
        gemm128_kernel<<<dim3(mg, 6), 256>>>(px, pBpool + (size_t)i * 128 * 384, pY, N, 384, 0);
        // pool accumulation + x = elu(x @ Wpsi)
        poolpsi_kernel<<<625, 256>>>(gidx, N);
    }

    final_kernel<<<(G + 7) / 8, 256>>>(Wlr1, Wlr2, Wlr3, out, G);
}

// round 13
// speedup vs baseline: 1.8043x; 1.0427x over previous
#include <cuda_runtime.h>

#define NN 20000
#define EE 320000
#define GG 200
#define FF 128

// ---- scratch (static device globals: allocation-free at runtime) ----
__device__ float g_x[NN * FF];            // node features
__device__ float g_P[NN * 768];           // per-node gate/mlp projections [Ag|Bg|Cg|Am|Bm|Cm]
__device__ float g_Y[NN * 384];           // per-node [y_p1|y_p2|y_psi]
__device__ float g_pool[GG * FF];         // accumulated pools
__device__ float g_Bcat[3 * 128 * 768];   // packed gate/mlp weights per block
__device__ float g_Bpool[3 * 128 * 384];  // packed pool/psi weights per block

typedef unsigned long long ull;

__device__ __forceinline__ float sigm(float v) { return 1.0f / (1.0f + __expf(-v)); }
__device__ __forceinline__ float eluf(float v) { return v > 0.f ? v : (__expf(v) - 1.0f); }

__device__ __forceinline__ void fma2(ull& acc, ull a, ull b) {
    asm("fma.rn.f32x2 %0, %1, %2, %0;" : "+l"(acc) : "l"(a), "l"(b));
}
__device__ __forceinline__ ull mul2(ull a, ull b) {
    ull r; asm("mul.rn.f32x2 %0, %1, %2;" : "=l"(r) : "l"(a), "l"(b)); return r;
}
__device__ __forceinline__ float2 unp(ull v) {
    float2 r; asm("mov.b64 {%0,%1}, %2;" : "=f"(r.x), "=f"(r.y) : "l"(v)); return r;
}
__device__ __forceinline__ ull pk(float a, float b) {
    ull r; asm("mov.b64 %0, {%1,%2};" : "=l"(r) : "f"(a), "f"(b)); return r;
}

// Vector reduction: one red.global.add.v4.f32 replaces 4 scalar REDG ops.
__device__ __forceinline__ void red_add_v4(float* addr, float a, float b, float c, float d) {
    asm volatile("red.global.add.v4.f32 [%0], {%1, %2, %3, %4};"
                 :: "l"(addr), "f"(a), "f"(b), "f"(c), "f"(d) : "memory");
}

// =====================================================================
// Generic GEMM (R3-proven): C[M,N] = act(A[M,128] @ B[128,N]); N % 64 == 0
// BM=64, BN=64, BK=64 (2 k-tiles), 256 threads, 4x4 micro-tile
// =====================================================================
__global__ __launch_bounds__(256) void gemm128_kernel(
    const float* __restrict__ A, const float* __restrict__ B, float* __restrict__ C,
    int M, int N, int act)
{
    __shared__ float As[64][68];   // [m][k], padded: conflict-free scalar a-reads
    __shared__ float Bs[64][64];   // [k][n]

    int m0 = blockIdx.x * 64;
    int n0 = blockIdx.y * 64;
    int tid = threadIdx.x;
    int tx = tid & 15, ty = tid >> 4;

    float acc[4][4] = {};

    for (int kt = 0; kt < 2; kt++) {
        int k0 = kt * 64;
        #pragma unroll
        for (int i = 0; i < 4; i++) {
            int idx = tid + i * 256;        // 0..1023
            int r = idx >> 4;               // 0..63
            int cv = idx & 15;              // float4 within 64
            int m = m0 + r;
            float4 va = make_float4(0.f, 0.f, 0.f, 0.f);
            if (m < M) va = *(const float4*)(A + (size_t)m * 128 + k0 + cv * 4);
            *(float4*)(&As[r][cv * 4]) = va;
            float4 vb = *(const float4*)(B + (size_t)(k0 + r) * N + n0 + cv * 4);
            *(float4*)(&Bs[r][cv * 4]) = vb;
        }
        __syncthreads();
        #pragma unroll 8
        for (int k = 0; k < 64; k++) {
            float a0 = As[ty * 4 + 0][k];
            float a1 = As[ty * 4 + 1][k];
            float a2 = As[ty * 4 + 2][k];
            float a3 = As[ty * 4 + 3][k];
            float4 b = *(float4*)(&Bs[k][tx * 4]);
            acc[0][0] += a0 * b.x; acc[0][1] += a0 * b.y; acc[0][2] += a0 * b.z; acc[0][3] += a0 * b.w;
            acc[1][0] += a1 * b.x; acc[1][1] += a1 * b.y; acc[1][2] += a1 * b.z; acc[1][3] += a1 * b.w;
            acc[2][0] += a2 * b.x; acc[2][1] += a2 * b.y; acc[2][2] += a2 * b.z; acc[2][3] += a2 * b.w;
            acc[3][0] += a3 * b.x; acc[3][1] += a3 * b.y; acc[3][2] += a3 * b.z; acc[3][3] += a3 * b.w;
        }
        __syncthreads();
    }

    #pragma unroll
    for (int i = 0; i < 4; i++) {
        int m = m0 + ty * 4 + i;
        if (m < M) {
            float4 r;
            r.x = acc[i][0]; r.y = acc[i][1]; r.z = acc[i][2]; r.w = acc[i][3];
            if (act == 1) { r.x = sigm(r.x); r.y = sigm(r.y); r.z = sigm(r.z); r.w = sigm(r.w); }
            *(float4*)(C + (size_t)m * N + n0 + tx * 4) = r;
        }
    }
}

// =====================================================================
// Weight packing (recomputed every call)
// =====================================================================
__global__ void pack_gates_kernel(const float* __restrict__ Wg, const float* __restrict__ Wm)
{
    int idx = blockIdx.x * blockDim.x + threadIdx.x;
    if (idx >= 3 * 128 * 768) return;
    int j = idx % 768;
    int k = (idx / 768) % 128;
    int i = idx / (768 * 128);
    int b = j >> 7, c = j & 127;
    float v;
    if (b < 3) v = Wg[(size_t)i * 384 * 128 + (size_t)(b * 128 + k) * 128 + c];
    else       v = Wm[(size_t)i * 384 * 128 + (size_t)((b - 3) * 128 + k) * 128 + c];
    g_Bcat[idx] = v;
}

__global__ void pack_pool_kernel(const float* __restrict__ Wp1, const float* __restrict__ Wp2,
                                 const float* __restrict__ Wpsi)
{
    int idx = blockIdx.x * blockDim.x + threadIdx.x;
    if (idx >= 3 * 128 * 384) return;
    int j = idx % 384;
    int k = (idx / 384) % 128;
    int i = idx / (384 * 128);
    int b = j >> 7, c = j & 127;
    const float* W = (b == 0) ? Wp1 : (b == 1) ? Wp2 : Wpsi;
    g_Bpool[idx] = W[(size_t)i * 128 * 128 + (size_t)k * 128 + c];
}

__global__ void zero_pool_kernel()
{
    int i = blockIdx.x * blockDim.x + threadIdx.x;
    if (i < GG * FF) g_pool[i] = 0.f;
}

// =====================================================================
// Edge kernel (R5/R8-proven core): tiles of 64 edges per CTA iter,
// 8 edges/warp; scatter now via red.global.add.v4.f32 (1 op vs 4).
// =====================================================================
__global__ __launch_bounds__(256) void edge_kernel(
    const int* __restrict__ esrc, const int* __restrict__ etgt,
    const float* __restrict__ edist,
    const float* __restrict__ cs, const float* __restrict__ pw,
    const float* __restrict__ W1v, const float* __restrict__ W2v,
    const float* __restrict__ W2vg, int E)
{
    extern __shared__ float smem[];
    float*  sW = smem;                       // 88*128 floats = 45056 B
    float2* sC = (float2*)(smem + 88 * 128); // [64 edges][64 kslots] dup'd = 32768 B

    for (int i = threadIdx.x; i < 36 * 128; i += 256) sW[i] = W1v[i];
    for (int i = threadIdx.x; i < 26 * 128; i += 256) sW[36 * 128 + i] = W2v[i];
    for (int i = threadIdx.x; i < 26 * 128; i += 256) sW[62 * 128 + i] = W2vg[i];
    __syncthreads();

    int tid = threadIdx.x;
    int lane = tid & 31;
    int warp = tid >> 5;
    int f0 = lane * 4;
    int eb = warp * 8;
    int ntiles = (E + 63) >> 6;

    for (int tile = blockIdx.x; tile < ntiles; tile += gridDim.x) {
        int e0 = tile * 64;
        for (int idx = tid; idx < 64 * 36; idx += 256) {
            int e = idx / 36, k = idx % 36;
            if (e0 + e < E) {
                float v = cs[(size_t)(e0 + e) * 36 + k];
                sC[e * 64 + k] = make_float2(v, v);
            }
        }
        for (int idx = tid; idx < 64 * 26; idx += 256) {
            int e = idx / 26, k = idx % 26;
            if (e0 + e < E) {
                float v = pw[(size_t)(e0 + e) * 26 + k];
                sC[e * 64 + 36 + k] = make_float2(v, v);
            }
        }
        __syncthreads();

        // ---- phase A: zg = pw @ W2vg ----
        ull zg[8][2];
        #pragma unroll
        for (int e = 0; e < 8; e++) { zg[e][0] = 0ull; zg[e][1] = 0ull; }
        for (int kc = 0; kc < 13; kc++) {
            float4 w0 = *(float4*)(&sW[(62 + kc * 2) * 128 + f0]);
            float4 w1 = *(float4*)(&sW[(63 + kc * 2) * 128 + f0]);
            ull w0a = ((ull*)&w0)[0], w0b = ((ull*)&w0)[1];
            ull w1a = ((ull*)&w1)[0], w1b = ((ull*)&w1)[1];
            #pragma unroll
            for (int e = 0; e < 8; e++) {
                float4 cc = *(float4*)(&sC[(eb + e) * 64 + 36 + kc * 2]);
                ull c0 = ((ull*)&cc)[0], c1 = ((ull*)&cc)[1];
                fma2(zg[e][0], c0, w0a); fma2(zg[e][1], c0, w0b);
                fma2(zg[e][0], c1, w1a); fma2(zg[e][1], c1, w1b);
            }
        }
        ull ss[8][2];
        #pragma unroll
        for (int e = 0; e < 8; e++) {
            #pragma unroll
            for (int h = 0; h < 2; h++) {
                float2 v = unp(zg[e][h]);
                ss[e][h] = pk(sigm(v.x), sigm(v.y));
            }
        }

        // ---- phase B: za = pw @ W2v, then za *= ss ----
        ull za[8][2];
        #pragma unroll
        for (int e = 0; e < 8; e++) { za[e][0] = 0ull; za[e][1] = 0ull; }
        for (int kc = 0; kc < 13; kc++) {
            float4 w0 = *(float4*)(&sW[(36 + kc * 2) * 128 + f0]);
            float4 w1 = *(float4*)(&sW[(37 + kc * 2) * 128 + f0]);
            ull w0a = ((ull*)&w0)[0], w0b = ((ull*)&w0)[1];
            ull w1a = ((ull*)&w1)[0], w1b = ((ull*)&w1)[1];
            #pragma unroll
            for (int e = 0; e < 8; e++) {
                float4 cc = *(float4*)(&sC[(eb + e) * 64 + 36 + kc * 2]);
                ull c0 = ((ull*)&cc)[0], c1 = ((ull*)&cc)[1];
                fma2(za[e][0], c0, w0a); fma2(za[e][1], c0, w0b);
                fma2(za[e][0], c1, w1a); fma2(za[e][1], c1, w1b);
            }
        }
        #pragma unroll
        for (int e = 0; e < 8; e++) {
            za[e][0] = mul2(za[e][0], ss[e][0]);
            za[e][1] = mul2(za[e][1], ss[e][1]);
        }

        // ---- phase C: za += cs @ W1v ----
        for (int kc = 0; kc < 18; kc++) {
            float4 w0 = *(float4*)(&sW[(kc * 2) * 128 + f0]);
            float4 w1 = *(float4*)(&sW[(kc * 2 + 1) * 128 + f0]);
            ull w0a = ((ull*)&w0)[0], w0b = ((ull*)&w0)[1];
            ull w1a = ((ull*)&w1)[0], w1b = ((ull*)&w1)[1];
            #pragma unroll
            for (int e = 0; e < 8; e++) {
                float4 cc = *(float4*)(&sC[(eb + e) * 64 + kc * 2]);
                ull c0 = ((ull*)&cc)[0], c1 = ((ull*)&cc)[1];
                fma2(za[e][0], c0, w0a); fma2(za[e][1], c0, w0b);
                fma2(za[e][0], c1, w1a); fma2(za[e][1], c1, w1b);
            }
        }

        // ---- gate phase ----
        int sreg = 0, treg = 0; float dreg = 1.f;
        if (lane < 8 && (e0 + eb + lane) < E) {
            sreg = esrc[e0 + eb + lane];
            treg = etgt[e0 + eb + lane];
            dreg = edist[e0 + eb + lane];
        }
        #pragma unroll
        for (int e = 0; e < 8; e++) {
            int s = __shfl_sync(0xffffffffu, sreg, e);
            int t = __shfl_sync(0xffffffffu, treg, e);
            float invd = 1.0f / __shfl_sync(0xffffffffu, dreg, e);
            if ((e0 + eb + e) < E) {
                const float* Ps = g_P + (size_t)s * 768;
                const float* Pt = g_P + (size_t)t * 768;
                float4 ag  = *(const float4*)(Ps + f0);
                float4 bg  = *(const float4*)(Pt + 128 + f0);
                float4 cgs = *(const float4*)(Ps + 256 + f0);
                float4 cgt = *(const float4*)(Pt + 256 + f0);
                float4 am  = *(const float4*)(Ps + 384 + f0);
                float4 bm  = *(const float4*)(Pt + 512 + f0);
                float4 cms = *(const float4*)(Ps + 640 + f0);
                float4 cmt = *(const float4*)(Pt + 640 + f0);

                float2 za0 = unp(za[e][0]);
                float2 za1 = unp(za[e][1]);
                float zv[4] = { za0.x, za0.y, za1.x, za1.y };
                float gv[4], mv[4];
                gv[0] = sigm(ag.x + bg.x + (cgt.x - cgs.x) * invd);
                gv[1] = sigm(ag.y + bg.y + (cgt.y - cgs.y) * invd);
                gv[2] = sigm(ag.z + bg.z + (cgt.z - cgs.z) * invd);
                gv[3] = sigm(ag.w + bg.w + (cgt.w - cgs.w) * invd);
                mv[0] = eluf(am.x + bm.x + (cmt.x - cms.x) * invd);
                mv[1] = eluf(am.y + bm.y + (cmt.y - cms.y) * invd);
                mv[2] = eluf(am.z + bm.z + (cmt.z - cms.z) * invd);
                mv[3] = eluf(am.w + bm.w + (cmt.w - cms.w) * invd);

                red_add_v4(g_x + (size_t)s * 128 + f0,
                           gv[0] * mv[0] * zv[0], gv[1] * mv[1] * zv[1],
                           gv[2] * mv[2] * zv[2], gv[3] * mv[3] * zv[3]);
            }
        }
        __syncthreads();
    }
}

// =====================================================================
// Pool + psi: per node, pool[g] += elu(y1)*y2 ; x = elu(y3)
// (pool scatter via red.global.add.v4.f32)
// =====================================================================
__global__ __launch_bounds__(256) void poolpsi_kernel(const int* __restrict__ gidx, int N)
{
    int lane = threadIdx.x & 31;
    int f0 = lane * 4;
    int warp = blockIdx.x * 8 + (threadIdx.x >> 5);
    int nw = gridDim.x * 8;
    for (int n = warp; n < N; n += nw) {
        int g = gidx[n];
        const float* yr = g_Y + (size_t)n * 384;
        float y1[4], y2[4], y3[4];
        *(float4*)y1 = *(const float4*)(yr + f0);
        *(float4*)y2 = *(const float4*)(yr + 128 + f0);
        *(float4*)y3 = *(const float4*)(yr + 256 + f0);
        red_add_v4(g_pool + (size_t)g * 128 + f0,
                   eluf(y1[0]) * y2[0], eluf(y1[1]) * y2[1],
                   eluf(y1[2]) * y2[2], eluf(y1[3]) * y2[3]);
        float xo[4];
        #pragma unroll
        for (int j = 0; j < 4; j++) xo[j] = eluf(y3[j]);
        *(float4*)(g_x + (size_t)n * 128 + f0) = *(float4*)xo;
    }
}

// =====================================================================
// Final MLP: one warp per graph.  128 -> 64 -> 42 -> 1
// =====================================================================
__global__ __launch_bounds__(256) void final_kernel(
    const float* __restrict__ W1, const float* __restrict__ W2,
    const float* __restrict__ W3, float* __restrict__ out, int G)
{
    int lane = threadIdx.x & 31;
    int warp = blockIdx.x * 8 + (threadIdx.x >> 5);
    int nw = gridDim.x * 8;
    for (int g = warp; g < G; g += nw) {
        float pr[4];
        #pragma unroll
        for (int c = 0; c < 4; c++) pr[c] = g_pool[(size_t)g * 128 + c * 32 + lane];

        float a0 = 0.f, a1 = 0.f;
        #pragma unroll
        for (int c = 0; c < 4; c++) {
            #pragma unroll
            for (int kk = 0; kk < 32; kk++) {
                float v = __shfl_sync(0xffffffffu, pr[c], kk);
                int k = c * 32 + kk;
                a0 += v * W1[k * 64 + lane * 2];
                a1 += v * W1[k * 64 + lane * 2 + 1];
            }
        }
        a0 = eluf(a0); a1 = eluf(a1);

        float b0 = 0.f, b1 = 0.f;
        #pragma unroll
        for (int k = 0; k < 64; k++) {
            float v = __shfl_sync(0xffffffffu, (k & 1) ? a1 : a0, k >> 1);
            b0 += v * W2[k * 42 + lane];
            if (lane < 10) b1 += v * W2[k * 42 + 32 + lane];
        }
        b0 = eluf(b0);
        if (lane < 10) b1 = eluf(b1);

        float r = b0 * W3[lane] + ((lane < 10) ? b1 * W3[32 + lane] : 0.f);
        #pragma unroll
        for (int o = 16; o; o >>= 1) r += __shfl_xor_sync(0xffffffffu, r, o);
        if (lane == 0) out[g] = r;
    }
}

// =====================================================================
extern "C" void kernel_launch(void* const* d_in, const int* in_sizes, int n_in,
                              void* d_out, int out_size)
{
    (void)n_in; (void)out_size;
    const float* nodes  = (const float*)d_in[0];
    const int*   esrc   = (const int*)d_in[1];
    const int*   etgt   = (const int*)d_in[2];
    const float* edist  = (const float*)d_in[3];
    const int*   gidx   = (const int*)d_in[4];
    const float* cs     = (const float*)d_in[6];
    const float* pw     = (const float*)d_in[7];
    const float* W_emb  = (const float*)d_in[8];
    const float* Wg     = (const float*)d_in[9];
    const float* Wm     = (const float*)d_in[10];
    const float* W1v    = (const float*)d_in[11];
    const float* W2v    = (const float*)d_in[12];
    const float* W2vg   = (const float*)d_in[13];
    const float* Wp1    = (const float*)d_in[14];
    const float* Wp2    = (const float*)d_in[15];
    const float* Wpsi   = (const float*)d_in[16];
    const float* Wlr1   = (const float*)d_in[17];
    const float* Wlr2   = (const float*)d_in[18];
    const float* Wlr3   = (const float*)d_in[19];
    float* out = (float*)d_out;

    int N = in_sizes[0] / FF;       // 20000
    int E = in_sizes[1];            // 320000
    int G = in_sizes[5];            // 200

    float *px, *pP, *pY, *pBcat, *pBpool;
    cudaGetSymbolAddress((void**)&px, g_x);
    cudaGetSymbolAddress((void**)&pP, g_P);
    cudaGetSymbolAddress((void**)&pY, g_Y);
    cudaGetSymbolAddress((void**)&pBcat, g_Bcat);
    cudaGetSymbolAddress((void**)&pBpool, g_Bpool);

    static int smem_set = 0;
    const int EDGE_SMEM = 88 * 128 * 4 + 64 * 64 * 8;  // 77824 B
    if (!smem_set) {
        cudaFuncSetAttribute(edge_kernel, cudaFuncAttributeMaxDynamicSharedMemorySize, EDGE_SMEM);
        smem_set = 1;
    }

    // prep
    pack_gates_kernel<<<(3 * 128 * 768 + 255) / 256, 256>>>(Wg, Wm);
    pack_pool_kernel<<<(3 * 128 * 384 + 255) / 256, 256>>>(Wp1, Wp2, Wpsi);
    zero_pool_kernel<<<(GG * FF + 255) / 256, 256>>>();

    int mg = (N + 63) / 64;   // 313

    // embedding: x = sigmoid(nodes @ W_emb)
    gemm128_kernel<<<dim3(mg, 2), 256>>>(nodes, W_emb, px, N, 128, 1);

    for (int i = 0; i < 3; i++) {
        // node-side gate/mlp projections: P = x @ Bcat[i]   [N, 768]
        gemm128_kernel<<<dim3(mg, 12), 256>>>(px, pBcat + (size_t)i * 128 * 768, pP, N, 768, 0);
        // edge pass: scatter-add z into x
        edge_kernel<<<296, 256, EDGE_SMEM>>>(esrc, etgt, edist, cs, pw,
                                             W1v + (size_t)i * 36 * 128,
                                             W2v + (size_t)i * 26 * 128,
                                             W2vg + (size_t)i * 26 * 128, E);
        // pool/psi projections: Y = x @ Bpool[i]   [N, 384]
        gemm128_kernel<<<dim3(mg, 6), 256>>>(px, pBpool + (size_t)i * 128 * 384, pY, N, 384, 0);
        // pool accumulation + x = elu(x @ Wpsi)
        poolpsi_kernel<<<625, 256>>>(gidx, N);
    }

    final_kernel<<<(G + 7) / 8, 256>>>(Wlr1, Wlr2, Wlr3, out, G);
}

// round 14
// speedup vs baseline: 1.8327x; 1.0157x over previous
#include <cuda_runtime.h>

#define NN 20000
#define EE 320000
#define GG 200
#define FF 128

// ---- scratch (static device globals: allocation-free at runtime) ----
__device__ float g_x[NN * FF];            // node features
__device__ float g_P[NN * 768];           // per-node gate/mlp projections [Ag|Bg|Cg|Am|Bm|Cm]
__device__ float g_Y[NN * 384];           // per-node [y_p1|y_p2|y_psi]
__device__ float g_pool[GG * FF];         // accumulated pools
__device__ float g_Bcat[3 * 128 * 768];   // packed gate/mlp weights per block
__device__ float g_Bpool[3 * 128 * 384];  // packed pool/psi weights per block

typedef unsigned long long ull;

__device__ __forceinline__ float sigm(float v) { return 1.0f / (1.0f + __expf(-v)); }
__device__ __forceinline__ float eluf(float v) { return v > 0.f ? v : (__expf(v) - 1.0f); }

__device__ __forceinline__ void fma2(ull& acc, ull a, ull b) {
    asm("fma.rn.f32x2 %0, %1, %2, %0;" : "+l"(acc) : "l"(a), "l"(b));
}
__device__ __forceinline__ ull mul2(ull a, ull b) {
    ull r; asm("mul.rn.f32x2 %0, %1, %2;" : "=l"(r) : "l"(a), "l"(b)); return r;
}
__device__ __forceinline__ float2 unp(ull v) {
    float2 r; asm("mov.b64 {%0,%1}, %2;" : "=f"(r.x), "=f"(r.y) : "l"(v)); return r;
}
__device__ __forceinline__ ull pk(float a, float b) {
    ull r; asm("mov.b64 %0, {%1,%2};" : "=l"(r) : "f"(a), "f"(b)); return r;
}

// Vector reduction: one red.global.add.v4.f32 replaces 4 scalar REDG ops.
__device__ __forceinline__ void red_add_v4(float* addr, float a, float b, float c, float d) {
    asm volatile("red.global.add.v4.f32 [%0], {%1, %2, %3, %4};"
                 :: "l"(addr), "f"(a), "f"(b), "f"(c), "f"(d) : "memory");
}

// =====================================================================
// Generic GEMM (R3-proven): C[M,N] = act(A[M,128] @ B[128,N]); N % 64 == 0
// BM=64, BN=64, BK=64 (2 k-tiles), 256 threads, 4x4 micro-tile
// =====================================================================
__global__ __launch_bounds__(256) void gemm128_kernel(
    const float* __restrict__ A, const float* __restrict__ B, float* __restrict__ C,
    int M, int N, int act)
{
    __shared__ float As[64][68];   // [m][k], padded: conflict-free scalar a-reads
    __shared__ float Bs[64][64];   // [k][n]

    int m0 = blockIdx.x * 64;
    int n0 = blockIdx.y * 64;
    int tid = threadIdx.x;
    int tx = tid & 15, ty = tid >> 4;

    float acc[4][4] = {};

    for (int kt = 0; kt < 2; kt++) {
        int k0 = kt * 64;
        #pragma unroll
        for (int i = 0; i < 4; i++) {
            int idx = tid + i * 256;        // 0..1023
            int r = idx >> 4;               // 0..63
            int cv = idx & 15;              // float4 within 64
            int m = m0 + r;
            float4 va = make_float4(0.f, 0.f, 0.f, 0.f);
            if (m < M) va = *(const float4*)(A + (size_t)m * 128 + k0 + cv * 4);
            *(float4*)(&As[r][cv * 4]) = va;
            float4 vb = *(const float4*)(B + (size_t)(k0 + r) * N + n0 + cv * 4);
            *(float4*)(&Bs[r][cv * 4]) = vb;
        }
        __syncthreads();
        #pragma unroll 8
        for (int k = 0; k < 64; k++) {
            float a0 = As[ty * 4 + 0][k];
            float a1 = As[ty * 4 + 1][k];
            float a2 = As[ty * 4 + 2][k];
            float a3 = As[ty * 4 + 3][k];
            float4 b = *(float4*)(&Bs[k][tx * 4]);
            acc[0][0] += a0 * b.x; acc[0][1] += a0 * b.y; acc[0][2] += a0 * b.z; acc[0][3] += a0 * b.w;
            acc[1][0] += a1 * b.x; acc[1][1] += a1 * b.y; acc[1][2] += a1 * b.z; acc[1][3] += a1 * b.w;
            acc[2][0] += a2 * b.x; acc[2][1] += a2 * b.y; acc[2][2] += a2 * b.z; acc[2][3] += a2 * b.w;
            acc[3][0] += a3 * b.x; acc[3][1] += a3 * b.y; acc[3][2] += a3 * b.z; acc[3][3] += a3 * b.w;
        }
        __syncthreads();
    }

    #pragma unroll
    for (int i = 0; i < 4; i++) {
        int m = m0 + ty * 4 + i;
        if (m < M) {
            float4 r;
            r.x = acc[i][0]; r.y = acc[i][1]; r.z = acc[i][2]; r.w = acc[i][3];
            if (act == 1) { r.x = sigm(r.x); r.y = sigm(r.y); r.z = sigm(r.z); r.w = sigm(r.w); }
            *(float4*)(C + (size_t)m * N + n0 + tx * 4) = r;
        }
    }
}

// =====================================================================
// Weight packing (recomputed every call)
// =====================================================================
__global__ void pack_gates_kernel(const float* __restrict__ Wg, const float* __restrict__ Wm)
{
    int idx = blockIdx.x * blockDim.x + threadIdx.x;
    if (idx >= 3 * 128 * 768) return;
    int j = idx % 768;
    int k = (idx / 768) % 128;
    int i = idx / (768 * 128);
    int b = j >> 7, c = j & 127;
    float v;
    if (b < 3) v = Wg[(size_t)i * 384 * 128 + (size_t)(b * 128 + k) * 128 + c];
    else       v = Wm[(size_t)i * 384 * 128 + (size_t)((b - 3) * 128 + k) * 128 + c];
    g_Bcat[idx] = v;
}

__global__ void pack_pool_kernel(const float* __restrict__ Wp1, const float* __restrict__ Wp2,
                                 const float* __restrict__ Wpsi)
{
    int idx = blockIdx.x * blockDim.x + threadIdx.x;
    if (idx >= 3 * 128 * 384) return;
    int j = idx % 384;
    int k = (idx / 384) % 128;
    int i = idx / (384 * 128);
    int b = j >> 7, c = j & 127;
    const float* W = (b == 0) ? Wp1 : (b == 1) ? Wp2 : Wpsi;
    g_Bpool[idx] = W[(size_t)i * 128 * 128 + (size_t)k * 128 + c];
}

__global__ void zero_pool_kernel()
{
    int i = blockIdx.x * blockDim.x + threadIdx.x;
    if (i < GG * FF) g_pool[i] = 0.f;
}

// =====================================================================
// Edge kernel: tiles of 64 edges per CTA iter, 8 edges/warp.
// Coefficients staged UNDUPLICATED (plain float, LDS.64 reads = half
// the crossbar bytes); splat to packed f32x2 at use (1 mov.b64).
// =====================================================================
__global__ __launch_bounds__(256) void edge_kernel(
    const int* __restrict__ esrc, const int* __restrict__ etgt,
    const float* __restrict__ edist,
    const float* __restrict__ cs, const float* __restrict__ pw,
    const float* __restrict__ W1v, const float* __restrict__ W2v,
    const float* __restrict__ W2vg, int E)
{
    extern __shared__ float smem[];
    float* sW = smem;                 // 88*128 floats = 45056 B
    float* sC = smem + 88 * 128;      // [64 edges][64 kslots] plain = 16384 B

    for (int i = threadIdx.x; i < 36 * 128; i += 256) sW[i] = W1v[i];
    for (int i = threadIdx.x; i < 26 * 128; i += 256) sW[36 * 128 + i] = W2v[i];
    for (int i = threadIdx.x; i < 26 * 128; i += 256) sW[62 * 128 + i] = W2vg[i];
    __syncthreads();

    int tid = threadIdx.x;
    int lane = tid & 31;
    int warp = tid >> 5;
    int f0 = lane * 4;
    int eb = warp * 8;
    int ntiles = (E + 63) >> 6;

    for (int tile = blockIdx.x; tile < ntiles; tile += gridDim.x) {
        int e0 = tile * 64;
        for (int idx = tid; idx < 64 * 36; idx += 256) {
            int e = idx / 36, k = idx % 36;
            if (e0 + e < E) sC[e * 64 + k] = cs[(size_t)(e0 + e) * 36 + k];
        }
        for (int idx = tid; idx < 64 * 26; idx += 256) {
            int e = idx / 26, k = idx % 26;
            if (e0 + e < E) sC[e * 64 + 36 + k] = pw[(size_t)(e0 + e) * 26 + k];
        }
        __syncthreads();

        // ---- phase A: zg = pw @ W2vg ----
        ull zg[8][2];
        #pragma unroll
        for (int e = 0; e < 8; e++) { zg[e][0] = 0ull; zg[e][1] = 0ull; }
        for (int kc = 0; kc < 13; kc++) {
            float4 w0 = *(float4*)(&sW[(62 + kc * 2) * 128 + f0]);
            float4 w1 = *(float4*)(&sW[(63 + kc * 2) * 128 + f0]);
            ull w0a = ((ull*)&w0)[0], w0b = ((ull*)&w0)[1];
            ull w1a = ((ull*)&w1)[0], w1b = ((ull*)&w1)[1];
            #pragma unroll
            for (int e = 0; e < 8; e++) {
                float2 cc = *(float2*)(&sC[(eb + e) * 64 + 36 + kc * 2]);
                ull c0 = pk(cc.x, cc.x);
                ull c1 = pk(cc.y, cc.y);
                fma2(zg[e][0], c0, w0a); fma2(zg[e][1], c0, w0b);
                fma2(zg[e][0], c1, w1a); fma2(zg[e][1], c1, w1b);
            }
        }
        ull ss[8][2];
        #pragma unroll
        for (int e = 0; e < 8; e++) {
            #pragma unroll
            for (int h = 0; h < 2; h++) {
                float2 v = unp(zg[e][h]);
                ss[e][h] = pk(sigm(v.x), sigm(v.y));
            }
        }

        // ---- phase B: za = pw @ W2v, then za *= ss ----
        ull za[8][2];
        #pragma unroll
        for (int e = 0; e < 8; e++) { za[e][0] = 0ull; za[e][1] = 0ull; }
        for (int kc = 0; kc < 13; kc++) {
            float4 w0 = *(float4*)(&sW[(36 + kc * 2) * 128 + f0]);
            float4 w1 = *(float4*)(&sW[(37 + kc * 2) * 128 + f0]);
            ull w0a = ((ull*)&w0)[0], w0b = ((ull*)&w0)[1];
            ull w1a = ((ull*)&w1)[0], w1b = ((ull*)&w1)[1];
            #pragma unroll
            for (int e = 0; e < 8; e++) {
                float2 cc = *(float2*)(&sC[(eb + e) * 64 + 36 + kc * 2]);
                ull c0 = pk(cc.x, cc.x);
                ull c1 = pk(cc.y, cc.y);
                fma2(za[e][0], c0, w0a); fma2(za[e][1], c0, w0b);
                fma2(za[e][0], c1, w1a); fma2(za[e][1], c1, w1b);
            }
        }
        #pragma unroll
        for (int e = 0; e < 8; e++) {
            za[e][0] = mul2(za[e][0], ss[e][0]);
            za[e][1] = mul2(za[e][1], ss[e][1]);
        }

        // ---- phase C: za += cs @ W1v ----
        for (int kc = 0; kc < 18; kc++) {
            float4 w0 = *(float4*)(&sW[(kc * 2) * 128 + f0]);
            float4 w1 = *(float4*)(&sW[(kc * 2 + 1) * 128 + f0]);
            ull w0a = ((ull*)&w0)[0], w0b = ((ull*)&w0)[1];
            ull w1a = ((ull*)&w1)[0], w1b = ((ull*)&w1)[1];
            #pragma unroll
            for (int e = 0; e < 8; e++) {
                float2 cc = *(float2*)(&sC[(eb + e) * 64 + kc * 2]);
                ull c0 = pk(cc.x, cc.x);
                ull c1 = pk(cc.y, cc.y);
                fma2(za[e][0], c0, w0a); fma2(za[e][1], c0, w0b);
                fma2(za[e][0], c1, w1a); fma2(za[e][1], c1, w1b);
            }
        }

        // ---- gate phase ----
        int sreg = 0, treg = 0; float dreg = 1.f;
        if (lane < 8 && (e0 + eb + lane) < E) {
            sreg = esrc[e0 + eb + lane];
            treg = etgt[e0 + eb + lane];
            dreg = edist[e0 + eb + lane];
        }
        #pragma unroll
        for (int e = 0; e < 8; e++) {
            int s = __shfl_sync(0xffffffffu, sreg, e);
            int t = __shfl_sync(0xffffffffu, treg, e);
            float invd = 1.0f / __shfl_sync(0xffffffffu, dreg, e);
            if ((e0 + eb + e) < E) {
                const float* Ps = g_P + (size_t)s * 768;
                const float* Pt = g_P + (size_t)t * 768;
                float4 ag  = *(const float4*)(Ps + f0);
                float4 bg  = *(const float4*)(Pt + 128 + f0);
                float4 cgs = *(const float4*)(Ps + 256 + f0);
                float4 cgt = *(const float4*)(Pt + 256 + f0);
                float4 am  = *(const float4*)(Ps + 384 + f0);
                float4 bm  = *(const float4*)(Pt + 512 + f0);
                float4 cms = *(const float4*)(Ps + 640 + f0);
                float4 cmt = *(const float4*)(Pt + 640 + f0);

                float2 za0 = unp(za[e][0]);
                float2 za1 = unp(za[e][1]);
                float zv[4] = { za0.x, za0.y, za1.x, za1.y };
                float gv[4], mv[4];
                gv[0] = sigm(ag.x + bg.x + (cgt.x - cgs.x) * invd);
                gv[1] = sigm(ag.y + bg.y + (cgt.y - cgs.y) * invd);
                gv[2] = sigm(ag.z + bg.z + (cgt.z - cgs.z) * invd);
                gv[3] = sigm(ag.w + bg.w + (cgt.w - cgs.w) * invd);
                mv[0] = eluf(am.x + bm.x + (cmt.x - cms.x) * invd);
                mv[1] = eluf(am.y + bm.y + (cmt.y - cms.y) * invd);
                mv[2] = eluf(am.z + bm.z + (cmt.z - cms.z) * invd);
                mv[3] = eluf(am.w + bm.w + (cmt.w - cms.w) * invd);

                red_add_v4(g_x + (size_t)s * 128 + f0,
                           gv[0] * mv[0] * zv[0], gv[1] * mv[1] * zv[1],
                           gv[2] * mv[2] * zv[2], gv[3] * mv[3] * zv[3]);
            }
        }
        __syncthreads();
    }
}

// =====================================================================
// Pool + psi: per node, pool[g] += elu(y1)*y2 ; x = elu(y3)
// =====================================================================
__global__ __launch_bounds__(256) void poolpsi_kernel(const int* __restrict__ gidx, int N)
{
    int lane = threadIdx.x & 31;
    int f0 = lane * 4;
    int warp = blockIdx.x * 8 + (threadIdx.x >> 5);
    int nw = gridDim.x * 8;
    for (int n = warp; n < N; n += nw) {
        int g = gidx[n];
        const float* yr = g_Y + (size_t)n * 384;
        float y1[4], y2[4], y3[4];
        *(float4*)y1 = *(const float4*)(yr + f0);
        *(float4*)y2 = *(const float4*)(yr + 128 + f0);
        *(float4*)y3 = *(const float4*)(yr + 256 + f0);
        red_add_v4(g_pool + (size_t)g * 128 + f0,
                   eluf(y1[0]) * y2[0], eluf(y1[1]) * y2[1],
                   eluf(y1[2]) * y2[2], eluf(y1[3]) * y2[3]);
        float xo[4];
        #pragma unroll
        for (int j = 0; j < 4; j++) xo[j] = eluf(y3[j]);
        *(float4*)(g_x + (size_t)n * 128 + f0) = *(float4*)xo;
    }
}

// =====================================================================
// Final MLP: one warp per graph.  128 -> 64 -> 42 -> 1
// =====================================================================
__global__ __launch_bounds__(256) void final_kernel(
    const float* __restrict__ W1, const float* __restrict__ W2,
    const float* __restrict__ W3, float* __restrict__ out, int G)
{
    int lane = threadIdx.x & 31;
    int warp = blockIdx.x * 8 + (threadIdx.x >> 5);
    int nw = gridDim.x * 8;
    for (int g = warp; g < G; g += nw) {
        float pr[4];
        #pragma unroll
        for (int c = 0; c < 4; c++) pr[c] = g_pool[(size_t)g * 128 + c * 32 + lane];

        float a0 = 0.f, a1 = 0.f;
        #pragma unroll
        for (int c = 0; c < 4; c++) {
            #pragma unroll
            for (int kk = 0; kk < 32; kk++) {
                float v = __shfl_sync(0xffffffffu, pr[c], kk);
                int k = c * 32 + kk;
                a0 += v * W1[k * 64 + lane * 2];
                a1 += v * W1[k * 64 + lane * 2 + 1];
            }
        }
        a0 = eluf(a0); a1 = eluf(a1);

        float b0 = 0.f, b1 = 0.f;
        #pragma unroll
        for (int k = 0; k < 64; k++) {
            float v = __shfl_sync(0xffffffffu, (k & 1) ? a1 : a0, k >> 1);
            b0 += v * W2[k * 42 + lane];
            if (lane < 10) b1 += v * W2[k * 42 + 32 + lane];
        }
        b0 = eluf(b0);
        if (lane < 10) b1 = eluf(b1);

        float r = b0 * W3[lane] + ((lane < 10) ? b1 * W3[32 + lane] : 0.f);
        #pragma unroll
        for (int o = 16; o; o >>= 1) r += __shfl_xor_sync(0xffffffffu, r, o);
        if (lane == 0) out[g] = r;
    }
}

// =====================================================================
extern "C" void kernel_launch(void* const* d_in, const int* in_sizes, int n_in,
                              void* d_out, int out_size)
{
    (void)n_in; (void)out_size;
    const float* nodes  = (const float*)d_in[0];
    const int*   esrc   = (const int*)d_in[1];
    const int*   etgt   = (const int*)d_in[2];
    const float* edist  = (const float*)d_in[3];
    const int*   gidx   = (const int*)d_in[4];
    const float* cs     = (const float*)d_in[6];
    const float* pw     = (const float*)d_in[7];
    const float* W_emb  = (const float*)d_in[8];
    const float* Wg     = (const float*)d_in[9];
    const float* Wm     = (const float*)d_in[10];
    const float* W1v    = (const float*)d_in[11];
    const float* W2v    = (const float*)d_in[12];
    const float* W2vg   = (const float*)d_in[13];
    const float* Wp1    = (const float*)d_in[14];
    const float* Wp2    = (const float*)d_in[15];
    const float* Wpsi   = (const float*)d_in[16];
    const float* Wlr1   = (const float*)d_in[17];
    const float* Wlr2   = (const float*)d_in[18];
    const float* Wlr3   = (const float*)d_in[19];
    float* out = (float*)d_out;

    int N = in_sizes[0] / FF;       // 20000
    int E = in_sizes[1];            // 320000
    int G = in_sizes[5];            // 200

    float *px, *pP, *pY, *pBcat, *pBpool;
    cudaGetSymbolAddress((void**)&px, g_x);
    cudaGetSymbolAddress((void**)&pP, g_P);
    cudaGetSymbolAddress((void**)&pY, g_Y);
    cudaGetSymbolAddress((void**)&pBcat, g_Bcat);
    cudaGetSymbolAddress((void**)&pBpool, g_Bpool);

    static int smem_set = 0;
    const int EDGE_SMEM = 88 * 128 * 4 + 64 * 64 * 4;  // 61440 B
    if (!smem_set) {
        cudaFuncSetAttribute(edge_kernel, cudaFuncAttributeMaxDynamicSharedMemorySize, EDGE_SMEM);
        smem_set = 1;
    }

    // prep
    pack_gates_kernel<<<(3 * 128 * 768 + 255) / 256, 256>>>(Wg, Wm);
    pack_pool_kernel<<<(3 * 128 * 384 + 255) / 256, 256>>>(Wp1, Wp2, Wpsi);
    zero_pool_kernel<<<(GG * FF + 255) / 256, 256>>>();

    int mg = (N + 63) / 64;   // 313

    // embedding: x = sigmoid(nodes @ W_emb)
    gemm128_kernel<<<dim3(mg, 2), 256>>>(nodes, W_emb, px, N, 128, 1);

    for (int i = 0; i < 3; i++) {
        // node-side gate/mlp projections: P = x @ Bcat[i]   [N, 768]
        gemm128_kernel<<<dim3(mg, 12), 256>>>(px, pBcat + (size_t)i * 128 * 768, pP, N, 768, 0);
        // edge pass: scatter-add z into x
        edge_kernel<<<296, 256, EDGE_SMEM>>>(esrc, etgt, edist, cs, pw,
                                             W1v + (size_t)i * 36 * 128,
                                             W2v + (size_t)i * 26 * 128,
                                             W2vg + (size_t)i * 26 * 128, E);
        // pool/psi projections: Y = x @ Bpool[i]   [N, 384]
        gemm128_kernel<<<dim3(mg, 6), 256>>>(px, pBpool + (size_t)i * 128 * 384, pY, N, 384, 0);
        // pool accumulation + x = elu(x @ Wpsi)
        poolpsi_kernel<<<625, 256>>>(gidx, N);
    }

    final_kernel<<<(G + 7) / 8, 256>>>(Wlr1, Wlr2, Wlr3, out, G);
}

// round 16
// speedup vs baseline: 1.8664x; 1.0183x over previous
#include <cuda_runtime.h>

#define NN 20000
#define EE 320000
#define GG 200
#define FF 128

// ---- scratch (static device globals: allocation-free at runtime) ----
__device__ float g_x[NN * FF];            // node features
__device__ float g_P[NN * 768];           // per-node gate/mlp projections [Ag|Bg|Cg|Am|Bm|Cm]
__device__ float g_Y[NN * 384];           // per-node [y_p1|y_p2|y_psi]
__device__ float g_pool[GG * FF];         // accumulated pools
__device__ float g_Bcat[3 * 128 * 768];   // packed gate/mlp weights per block
__device__ float g_Bpool[3 * 128 * 384];  // packed pool/psi weights per block

typedef unsigned long long ull;

__device__ __forceinline__ float sigm(float v) { return 1.0f / (1.0f + __expf(-v)); }
__device__ __forceinline__ float eluf(float v) { return v > 0.f ? v : (__expf(v) - 1.0f); }

__device__ __forceinline__ void fma2(ull& acc, ull a, ull b) {
    asm("fma.rn.f32x2 %0, %1, %2, %0;" : "+l"(acc) : "l"(a), "l"(b));
}
__device__ __forceinline__ ull mul2(ull a, ull b) {
    ull r; asm("mul.rn.f32x2 %0, %1, %2;" : "=l"(r) : "l"(a), "l"(b)); return r;
}
__device__ __forceinline__ float2 unp(ull v) {
    float2 r; asm("mov.b64 {%0,%1}, %2;" : "=f"(r.x), "=f"(r.y) : "l"(v)); return r;
}
__device__ __forceinline__ ull pk(float a, float b) {
    ull r; asm("mov.b64 %0, {%1,%2};" : "=l"(r) : "f"(a), "f"(b)); return r;
}

// Vector reduction: one red.global.add.v4.f32 replaces 4 scalar REDG ops.
__device__ __forceinline__ void red_add_v4(float* addr, float a, float b, float c, float d) {
    asm volatile("red.global.add.v4.f32 [%0], {%1, %2, %3, %4};"
                 :: "l"(addr), "f"(a), "f"(b), "f"(c), "f"(d) : "memory");
}

// =====================================================================
// Generic GEMM (R3-proven): C[M,N] = act(A[M,128] @ B[128,N]); N % 64 == 0
// BM=64, BN=64, BK=64 (2 k-tiles), 256 threads, 4x4 micro-tile
// =====================================================================
__global__ __launch_bounds__(256) void gemm128_kernel(
    const float* __restrict__ A, const float* __restrict__ B, float* __restrict__ C,
    int M, int N, int act)
{
    __shared__ float As[64][68];   // [m][k], padded: conflict-free scalar a-reads
    __shared__ float Bs[64][64];   // [k][n]

    int m0 = blockIdx.x * 64;
    int n0 = blockIdx.y * 64;
    int tid = threadIdx.x;
    int tx = tid & 15, ty = tid >> 4;

    float acc[4][4] = {};

    for (int kt = 0; kt < 2; kt++) {
        int k0 = kt * 64;
        #pragma unroll
        for (int i = 0; i < 4; i++) {
            int idx = tid + i * 256;        // 0..1023
            int r = idx >> 4;               // 0..63
            int cv = idx & 15;              // float4 within 64
            int m = m0 + r;
            float4 va = make_float4(0.f, 0.f, 0.f, 0.f);
            if (m < M) va = *(const float4*)(A + (size_t)m * 128 + k0 + cv * 4);
            *(float4*)(&As[r][cv * 4]) = va;
            float4 vb = *(const float4*)(B + (size_t)(k0 + r) * N + n0 + cv * 4);
            *(float4*)(&Bs[r][cv * 4]) = vb;
        }
        __syncthreads();
        #pragma unroll 8
        for (int k = 0; k < 64; k++) {
            float a0 = As[ty * 4 + 0][k];
            float a1 = As[ty * 4 + 1][k];
            float a2 = As[ty * 4 + 2][k];
            float a3 = As[ty * 4 + 3][k];
            float4 b = *(float4*)(&Bs[k][tx * 4]);
            acc[0][0] += a0 * b.x; acc[0][1] += a0 * b.y; acc[0][2] += a0 * b.z; acc[0][3] += a0 * b.w;
            acc[1][0] += a1 * b.x; acc[1][1] += a1 * b.y; acc[1][2] += a1 * b.z; acc[1][3] += a1 * b.w;
            acc[2][0] += a2 * b.x; acc[2][1] += a2 * b.y; acc[2][2] += a2 * b.z; acc[2][3] += a2 * b.w;
            acc[3][0] += a3 * b.x; acc[3][1] += a3 * b.y; acc[3][2] += a3 * b.z; acc[3][3] += a3 * b.w;
        }
        __syncthreads();
    }

    #pragma unroll
    for (int i = 0; i < 4; i++) {
        int m = m0 + ty * 4 + i;
        if (m < M) {
            float4 r;
            r.x = acc[i][0]; r.y = acc[i][1]; r.z = acc[i][2]; r.w = acc[i][3];
            if (act == 1) { r.x = sigm(r.x); r.y = sigm(r.y); r.z = sigm(r.z); r.w = sigm(r.w); }
            *(float4*)(C + (size_t)m * N + n0 + tx * 4) = r;
        }
    }
}

// =====================================================================
// Weight packing (recomputed every call)
// =====================================================================
__global__ void pack_gates_kernel(const float* __restrict__ Wg, const float* __restrict__ Wm)
{
    int idx = blockIdx.x * blockDim.x + threadIdx.x;
    if (idx >= 3 * 128 * 768) return;
    int j = idx % 768;
    int k = (idx / 768) % 128;
    int i = idx / (768 * 128);
    int b = j >> 7, c = j & 127;
    float v;
    if (b < 3) v = Wg[(size_t)i * 384 * 128 + (size_t)(b * 128 + k) * 128 + c];
    else       v = Wm[(size_t)i * 384 * 128 + (size_t)((b - 3) * 128 + k) * 128 + c];
    g_Bcat[idx] = v;
}

__global__ void pack_pool_kernel(const float* __restrict__ Wp1, const float* __restrict__ Wp2,
                                 const float* __restrict__ Wpsi)
{
    int idx = blockIdx.x * blockDim.x + threadIdx.x;
    if (idx >= 3 * 128 * 384) return;
    int j = idx % 384;
    int k = (idx / 384) % 128;
    int i = idx / (384 * 128);
    int b = j >> 7, c = j & 127;
    const float* W = (b == 0) ? Wp1 : (b == 1) ? Wp2 : Wpsi;
    g_Bpool[idx] = W[(size_t)i * 128 * 128 + (size_t)k * 128 + c];
}

__global__ void zero_pool_kernel()
{
    int i = blockIdx.x * blockDim.x + threadIdx.x;
    if (i < GG * FF) g_pool[i] = 0.f;
}

// =====================================================================
// Edge kernel: tiles of 64 edges per CTA iter, 8 edges/warp.
// Phases A (pw@W2vg) and B (pw@W2v) MERGED: one coefficient load feeds
// both accumulators (saves 104 LDS.64 + 13 loop iters per warp-tile).
// =====================================================================
__global__ __launch_bounds__(256) void edge_kernel(
    const int* __restrict__ esrc, const int* __restrict__ etgt,
    const float* __restrict__ edist,
    const float* __restrict__ cs, const float* __restrict__ pw,
    const float* __restrict__ W1v, const float* __restrict__ W2v,
    const float* __restrict__ W2vg, int E)
{
    extern __shared__ float smem[];
    float* sW = smem;                 // 88*128 floats = 45056 B
    float* sC = smem + 88 * 128;      // [64 edges][64 kslots] plain = 16384 B

    for (int i = threadIdx.x; i < 36 * 128; i += 256) sW[i] = W1v[i];
    for (int i = threadIdx.x; i < 26 * 128; i += 256) sW[36 * 128 + i] = W2v[i];
    for (int i = threadIdx.x; i < 26 * 128; i += 256) sW[62 * 128 + i] = W2vg[i];
    __syncthreads();

    int tid = threadIdx.x;
    int lane = tid & 31;
    int warp = tid >> 5;
    int f0 = lane * 4;
    int eb = warp * 8;
    int ntiles = (E + 63) >> 6;

    for (int tile = blockIdx.x; tile < ntiles; tile += gridDim.x) {
        int e0 = tile * 64;
        for (int idx = tid; idx < 64 * 36; idx += 256) {
            int e = idx / 36, k = idx % 36;
            if (e0 + e < E) sC[e * 64 + k] = cs[(size_t)(e0 + e) * 36 + k];
        }
        for (int idx = tid; idx < 64 * 26; idx += 256) {
            int e = idx / 26, k = idx % 26;
            if (e0 + e < E) sC[e * 64 + 36 + k] = pw[(size_t)(e0 + e) * 26 + k];
        }
        __syncthreads();

        // ---- merged phase A+B: zg = pw @ W2vg, za = pw @ W2v ----
        ull zg[8][2], za[8][2];
        #pragma unroll
        for (int e = 0; e < 8; e++) {
            zg[e][0] = 0ull; zg[e][1] = 0ull;
            za[e][0] = 0ull; za[e][1] = 0ull;
        }
        for (int kc = 0; kc < 13; kc++) {
            float4 g0 = *(float4*)(&sW[(62 + kc * 2) * 128 + f0]);
            float4 g1 = *(float4*)(&sW[(63 + kc * 2) * 128 + f0]);
            float4 v0 = *(float4*)(&sW[(36 + kc * 2) * 128 + f0]);
            float4 v1 = *(float4*)(&sW[(37 + kc * 2) * 128 + f0]);
            ull g0a = ((ull*)&g0)[0], g0b = ((ull*)&g0)[1];
            ull g1a = ((ull*)&g1)[0], g1b = ((ull*)&g1)[1];
            ull v0a = ((ull*)&v0)[0], v0b = ((ull*)&v0)[1];
            ull v1a = ((ull*)&v1)[0], v1b = ((ull*)&v1)[1];
            #pragma unroll
            for (int e = 0; e < 8; e++) {
                float2 cc = *(float2*)(&sC[(eb + e) * 64 + 36 + kc * 2]);
                ull c0 = pk(cc.x, cc.x);
                ull c1 = pk(cc.y, cc.y);
                fma2(zg[e][0], c0, g0a); fma2(zg[e][1], c0, g0b);
                fma2(zg[e][0], c1, g1a); fma2(zg[e][1], c1, g1b);
                fma2(za[e][0], c0, v0a); fma2(za[e][1], c0, v0b);
                fma2(za[e][0], c1, v1a); fma2(za[e][1], c1, v1b);
            }
        }
        // sigmoid(zg) then za *= s
        #pragma unroll
        for (int e = 0; e < 8; e++) {
            #pragma unroll
            for (int h = 0; h < 2; h++) {
                float2 v = unp(zg[e][h]);
                za[e][h] = mul2(za[e][h], pk(sigm(v.x), sigm(v.y)));
            }
        }

        // ---- phase C: za += cs @ W1v ----
        for (int kc = 0; kc < 18; kc++) {
            float4 w0 = *(float4*)(&sW[(kc * 2) * 128 + f0]);
            float4 w1 = *(float4*)(&sW[(kc * 2 + 1) * 128 + f0]);
            ull w0a = ((ull*)&w0)[0], w0b = ((ull*)&w0)[1];
            ull w1a = ((ull*)&w1)[0], w1b = ((ull*)&w1)[1];
            #pragma unroll
            for (int e = 0; e < 8; e++) {
                float2 cc = *(float2*)(&sC[(eb + e) * 64 + kc * 2]);
                ull c0 = pk(cc.x, cc.x);
                ull c1 = pk(cc.y, cc.y);
                fma2(za[e][0], c0, w0a); fma2(za[e][1], c0, w0b);
                fma2(za[e][0], c1, w1a); fma2(za[e][1], c1, w1b);
            }
        }

        // ---- gate phase ----
        int sreg = 0, treg = 0; float dreg = 1.f;
        if (lane < 8 && (e0 + eb + lane) < E) {
            sreg = esrc[e0 + eb + lane];
            treg = etgt[e0 + eb + lane];
            dreg = edist[e0 + eb + lane];
        }
        #pragma unroll
        for (int e = 0; e < 8; e++) {
            int s = __shfl_sync(0xffffffffu, sreg, e);
            int t = __shfl_sync(0xffffffffu, treg, e);
            float invd = 1.0f / __shfl_sync(0xffffffffu, dreg, e);
            if ((e0 + eb + e) < E) {
                const float* Ps = g_P + (size_t)s * 768;
                const float* Pt = g_P + (size_t)t * 768;
                float4 ag  = *(const float4*)(Ps + f0);
                float4 bg  = *(const float4*)(Pt + 128 + f0);
                float4 cgs = *(const float4*)(Ps + 256 + f0);
                float4 cgt = *(const float4*)(Pt + 256 + f0);
                float4 am  = *(const float4*)(Ps + 384 + f0);
                float4 bm  = *(const float4*)(Pt + 512 + f0);
                float4 cms = *(const float4*)(Ps + 640 + f0);
                float4 cmt = *(const float4*)(Pt + 640 + f0);

                float2 za0 = unp(za[e][0]);
                float2 za1 = unp(za[e][1]);
                float zv[4] = { za0.x, za0.y, za1.x, za1.y };
                float gv[4], mv[4];
                gv[0] = sigm(ag.x + bg.x + (cgt.x - cgs.x) * invd);
                gv[1] = sigm(ag.y + bg.y + (cgt.y - cgs.y) * invd);
                gv[2] = sigm(ag.z + bg.z + (cgt.z - cgs.z) * invd);
                gv[3] = sigm(ag.w + bg.w + (cgt.w - cgs.w) * invd);
                mv[0] = eluf(am.x + bm.x + (cmt.x - cms.x) * invd);
                mv[1] = eluf(am.y + bm.y + (cmt.y - cms.y) * invd);
                mv[2] = eluf(am.z + bm.z + (cmt.z - cms.z) * invd);
                mv[3] = eluf(am.w + bm.w + (cmt.w - cms.w) * invd);

                red_add_v4(g_x + (size_t)s * 128 + f0,
                           gv[0] * mv[0] * zv[0], gv[1] * mv[1] * zv[1],
                           gv[2] * mv[2] * zv[2], gv[3] * mv[3] * zv[3]);
            }
        }
        __syncthreads();
    }
}

// =====================================================================
// Pool + psi: per node, pool[g] += elu(y1)*y2 ; x = elu(y3)
// =====================================================================
__global__ __launch_bounds__(256) void poolpsi_kernel(const int* __restrict__ gidx, int N)
{
    int lane = threadIdx.x & 31;
    int f0 = lane * 4;
    int warp = blockIdx.x * 8 + (threadIdx.x >> 5);
    int nw = gridDim.x * 8;
    for (int n = warp; n < N; n += nw) {
        int g = gidx[n];
        const float* yr = g_Y + (size_t)n * 384;
        float y1[4], y2[4], y3[4];
        *(float4*)y1 = *(const float4*)(yr + f0);
        *(float4*)y2 = *(const float4*)(yr + 128 + f0);
        *(float4*)y3 = *(const float4*)(yr + 256 + f0);
        red_add_v4(g_pool + (size_t)g * 128 + f0,
                   eluf(y1[0]) * y2[0], eluf(y1[1]) * y2[1],
                   eluf(y1[2]) * y2[2], eluf(y1[3]) * y2[3]);
        float xo[4];
        #pragma unroll
        for (int j = 0; j < 4; j++) xo[j] = eluf(y3[j]);
        *(float4*)(g_x + (size_t)n * 128 + f0) = *(float4*)xo;
    }
}

// =====================================================================
// Final MLP: one warp per graph.  128 -> 64 -> 42 -> 1
// =====================================================================
__global__ __launch_bounds__(256) void final_kernel(
    const float* __restrict__ W1, const float* __restrict__ W2,
    const float* __restrict__ W3, float* __restrict__ out, int G)
{
    int lane = threadIdx.x & 31;
    int warp = blockIdx.x * 8 + (threadIdx.x >> 5);
    int nw = gridDim.x * 8;
    for (int g = warp; g < G; g += nw) {
        float pr[4];
        #pragma unroll
        for (int c = 0; c < 4; c++) pr[c] = g_pool[(size_t)g * 128 + c * 32 + lane];

        float a0 = 0.f, a1 = 0.f;
        #pragma unroll
        for (int c = 0; c < 4; c++) {
            #pragma unroll
            for (int kk = 0; kk < 32; kk++) {
                float v = __shfl_sync(0xffffffffu, pr[c], kk);
                int k = c * 32 + kk;
                a0 += v * W1[k * 64 + lane * 2];
                a1 += v * W1[k * 64 + lane * 2 + 1];
            }
        }
        a0 = eluf(a0); a1 = eluf(a1);

        float b0 = 0.f, b1 = 0.f;
        #pragma unroll
        for (int k = 0; k < 64; k++) {
            float v = __shfl_sync(0xffffffffu, (k & 1) ? a1 : a0, k >> 1);
            b0 += v * W2[k * 42 + lane];
            if (lane < 10) b1 += v * W2[k * 42 + 32 + lane];
        }
        b0 = eluf(b0);
        if (lane < 10) b1 = eluf(b1);

        float r = b0 * W3[lane] + ((lane < 10) ? b1 * W3[32 + lane] : 0.f);
        #pragma unroll
        for (int o = 16; o; o >>= 1) r += __shfl_xor_sync(0xffffffffu, r, o);
        if (lane == 0) out[g] = r;
    }
}

// =====================================================================
extern "C" void kernel_launch(void* const* d_in, const int* in_sizes, int n_in,
                              void* d_out, int out_size)
{
    (void)n_in; (void)out_size;
    const float* nodes  = (const float*)d_in[0];
    const int*   esrc   = (const int*)d_in[1];
    const int*   etgt   = (const int*)d_in[2];
    const float* edist  = (const float*)d_in[3];
    const int*   gidx   = (const int*)d_in[4];
    const float* cs     = (const float*)d_in[6];
    const float* pw     = (const float*)d_in[7];
    const float* W_emb  = (const float*)d_in[8];
    const float* Wg     = (const float*)d_in[9];
    const float* Wm     = (const float*)d_in[10];
    const float* W1v    = (const float*)d_in[11];
    const float* W2v    = (const float*)d_in[12];
    const float* W2vg   = (const float*)d_in[13];
    const float* Wp1    = (const float*)d_in[14];
    const float* Wp2    = (const float*)d_in[15];
    const float* Wpsi   = (const float*)d_in[16];
    const float* Wlr1   = (const float*)d_in[17];
    const float* Wlr2   = (const float*)d_in[18];
    const float* Wlr3   = (const float*)d_in[19];
    float* out = (float*)d_out;

    int N = in_sizes[0] / FF;       // 20000
    int E = in_sizes[1];            // 320000
    int G = in_sizes[5];            // 200

    float *px, *pP, *pY, *pBcat, *pBpool;
    cudaGetSymbolAddress((void**)&px, g_x);
    cudaGetSymbolAddress((void**)&pP, g_P);
    cudaGetSymbolAddress((void**)&pY, g_Y);
    cudaGetSymbolAddress((void**)&pBcat, g_Bcat);
    cudaGetSymbolAddress((void**)&pBpool, g_Bpool);

    static int smem_set = 0;
    const int EDGE_SMEM = 88 * 128 * 4 + 64 * 64 * 4;  // 61440 B
    if (!smem_set) {
        cudaFuncSetAttribute(edge_kernel, cudaFuncAttributeMaxDynamicSharedMemorySize, EDGE_SMEM);
        smem_set = 1;
    }

    // prep
    pack_gates_kernel<<<(3 * 128 * 768 + 255) / 256, 256>>>(Wg, Wm);
    pack_pool_kernel<<<(3 * 128 * 384 + 255) / 256, 256>>>(Wp1, Wp2, Wpsi);
    zero_pool_kernel<<<(GG * FF + 255) / 256, 256>>>();

    int mg = (N + 63) / 64;   // 313

    // embedding: x = sigmoid(nodes @ W_emb)
    gemm128_kernel<<<dim3(mg, 2), 256>>>(nodes, W_emb, px, N, 128, 1);

    for (int i = 0; i < 3; i++) {
        // node-side gate/mlp projections: P = x @ Bcat[i]   [N, 768]
        gemm128_kernel<<<dim3(mg, 12), 256>>>(px, pBcat + (size_t)i * 128 * 768, pP, N, 768, 0);
        // edge pass: scatter-add z into x
        edge_kernel<<<296, 256, EDGE_SMEM>>>(esrc, etgt, edist, cs, pw,
                                             W1v + (size_t)i * 36 * 128,
                                             W2v + (size_t)i * 26 * 128,
                                             W2vg + (size_t)i * 26 * 128, E);
        // pool/psi projections: Y = x @ Bpool[i]   [N, 384]
        gemm128_kernel<<<dim3(mg, 6), 256>>>(px, pBpool + (size_t)i * 128 * 384, pY, N, 384, 0);
        // pool accumulation + x = elu(x @ Wpsi)
        poolpsi_kernel<<<625, 256>>>(gidx, N);
    }

    final_kernel<<<(G + 7) / 8, 256>>>(Wlr1, Wlr2, Wlr3, out, G);
}